// round 4
// baseline (speedup 1.0000x reference)
#include <cuda_runtime.h>
#include <math.h>
#include <stdint.h>

#define BATCH 4
#define T 2048
#define H 1024
#define NHEAD 16
#define HD 64
#define FF 4096
#define BT (BATCH * T)   // 8192 rows

// ---------------- scratch (allocation-free: __device__ globals) --------------
__device__ float g_q[BT * H];      // tf32-rounded, d-permuted
__device__ float g_k[BT * H];      // tf32-rounded, d-permuted
__device__ float g_v[BT * H];      // tf32-rounded
__device__ float g_x1[BT * H];     // x + attn_out (exact)
__device__ float g_x1r[BT * H];    // tf32-rounded, k-permuted x1
__device__ float g_xr[BT * H];     // tf32-rounded, k-permuted x
__device__ float g_h[BT * FF];     // tf32-rounded, k-permuted gelu(x1@W1+b1)
__device__ float g_wqt[H * H];     // transposed + rounded + k-permuted weights [N,K]
__device__ float g_wkt[H * H];
__device__ float g_wvt[H * H];
__device__ float g_w1t[H * FF];    // [FF, H]
__device__ float g_w2t[FF * H];    // [H, FF]

// ---------------- helpers ----------------------------------------------------
__device__ __forceinline__ uint32_t smem_u32(const void* p) {
    uint32_t a;
    asm("{ .reg .u64 t; cvta.to.shared.u64 t, %1; cvt.u32.u64 %0, t; }"
        : "=r"(a) : "l"(p));
    return a;
}
__device__ __forceinline__ float rna_tf32(float x) {
    uint32_t u;
    asm("cvt.rna.tf32.f32 %0, %1;" : "=r"(u) : "f"(x));
    return __uint_as_float(u);
}
__device__ __forceinline__ float ftanh(float x) {
    float y;
    asm("tanh.approx.f32 %0, %1;" : "=f"(y) : "f"(x));
    return y;
}
__device__ __forceinline__ float gelu_f(float x) {
    return 0.5f * x * (1.0f + ftanh(0.7978845608028654f * (x + 0.044715f * x * x * x)));
}
// physical position of logical k-index l within its 8-group: [k0,k4,k1,k5,k2,k6,k3,k7]
__device__ __forceinline__ int perm8(int l) {
    return (l < 4) ? (2 * l) : (2 * (l - 4) + 1);
}
__device__ __forceinline__ uint2 lds64(uint32_t addr) {
    uint2 v;
    asm volatile("ld.shared.v2.b32 {%0, %1}, [%2];" : "=r"(v.x), "=r"(v.y) : "r"(addr));
    return v;
}
__device__ __forceinline__ void mma8(float* d, uint32_t a0, uint32_t a1, uint32_t a2,
                                     uint32_t a3, uint32_t b0, uint32_t b1) {
    asm volatile(
        "mma.sync.aligned.m16n8k8.row.col.f32.tf32.tf32.f32 "
        "{%0,%1,%2,%3}, {%4,%5,%6,%7}, {%8,%9}, {%0,%1,%2,%3};"
        : "+f"(d[0]), "+f"(d[1]), "+f"(d[2]), "+f"(d[3])
        : "r"(a0), "r"(a1), "r"(a2), "r"(a3), "r"(b0), "r"(b1));
}

// ---------------- prep kernels ------------------------------------------------
__global__ void round_perm_k(const float* __restrict__ in, float* __restrict__ out, int n) {
    int i = (blockIdx.x * blockDim.x + threadIdx.x) * 8;
    if (i < n) {
        float4 lo = *(const float4*)(in + i);
        float4 hi = *(const float4*)(in + i + 4);
        float4 o0, o1;
        o0.x = rna_tf32(lo.x); o0.y = rna_tf32(hi.x);
        o0.z = rna_tf32(lo.y); o0.w = rna_tf32(hi.y);
        o1.x = rna_tf32(lo.z); o1.y = rna_tf32(hi.z);
        o1.z = rna_tf32(lo.w); o1.w = rna_tf32(hi.w);
        *(float4*)(out + i)     = o0;
        *(float4*)(out + i + 4) = o1;
    }
}

__global__ void transpose_rna_perm_k(const float* __restrict__ W, float* __restrict__ Wt,
                                     int K, int N) {
    __shared__ float t[32][33];
    int n0 = blockIdx.x * 32, k0 = blockIdx.y * 32;
    int tx = threadIdx.x, ty = threadIdx.y;
    #pragma unroll
    for (int j = ty; j < 32; j += 8)
        t[j][tx] = W[(size_t)(k0 + j) * N + n0 + tx];
    __syncthreads();
    int kk = k0 + tx;
    int kphys = (kk & ~7) + perm8(kk & 7);
    #pragma unroll
    for (int j = ty; j < 32; j += 8)
        Wt[(size_t)(n0 + j) * K + kphys] = rna_tf32(t[tx][j]);
}

// ---------------- tf32 mma.sync GEMM ------------------------------------------
// modes: 0 plain, 1 gelu+rna+perm, 2 +res, 3 rna+perm (q/k), 4 rna (v)
// mode==3 launch: z==2 output uses emode 4.
#define STAGE_BYTES 32768
#define GEMM_SMEM   (3 * STAGE_BYTES)

__global__ __launch_bounds__(256, 2)
void gemm_tf32(const float* __restrict__ A,
               const float* __restrict__ B0t, const float* __restrict__ B1t,
               const float* __restrict__ B2t,
               const float* __restrict__ bias0, const float* __restrict__ bias1,
               const float* __restrict__ bias2,
               float* __restrict__ C0, float* __restrict__ C1, float* __restrict__ C2,
               const float* __restrict__ res,
               int K, int N, int mode)
{
    extern __shared__ float sf[];
    const uint32_t sbase = smem_u32(sf);

    const float* Bt = B0t; const float* bias = bias0; float* C = C0;
    if (blockIdx.z == 1) { Bt = B1t; bias = bias1; C = C1; }
    else if (blockIdx.z == 2) { Bt = B2t; bias = bias2; C = C2; }
    int emode = mode;
    if (mode == 3 && blockIdx.z == 2) emode = 4;

    const int tid  = threadIdx.x;
    const int lane = tid & 31;
    const int w    = tid >> 5;
    const int g    = lane >> 2;
    const int c    = lane & 3;
    const int wm   = w & 3;
    const int wnn  = w >> 2;
    const int bx = blockIdx.x, by = blockIdx.y;
    const int nk = K >> 5;

    const int rowl = tid >> 3;
    const int cj   = tid & 7;
    const uint32_t soA = (uint32_t)(rowl * 128 + ((cj ^ (rowl & 7)) << 4));
    const float* gA = A  + (size_t)(by * 128 + rowl) * K + cj * 4;
    const float* gB = Bt + (size_t)(bx * 128 + rowl) * K + cj * 4;

    #pragma unroll
    for (int s = 0; s < 3; s++) {
        uint32_t sb = sbase + s * STAGE_BYTES;
        #pragma unroll
        for (int t = 0; t < 4; t++) {
            asm volatile("cp.async.cg.shared.global [%0], [%1], 16;"
                         :: "r"(sb + soA + t * 4096),
                            "l"(gA + (size_t)(32 * t) * K + s * 32) : "memory");
            asm volatile("cp.async.cg.shared.global [%0], [%1], 16;"
                         :: "r"(sb + 16384 + soA + t * 4096),
                            "l"(gB + (size_t)(32 * t) * K + s * 32) : "memory");
        }
        asm volatile("cp.async.commit_group;" ::: "memory");
    }

    float acc[2][8][4];
    #pragma unroll
    for (int mi = 0; mi < 2; mi++)
        #pragma unroll
        for (int ni = 0; ni < 8; ni++)
            #pragma unroll
            for (int r = 0; r < 4; r++) acc[mi][ni][r] = 0.0f;

    uint32_t aOffB[2][2], bOffB[8], coffB[4];
    #pragma unroll
    for (int mi = 0; mi < 2; mi++)
        #pragma unroll
        for (int p = 0; p < 2; p++)
            aOffB[mi][p] = (uint32_t)((wm * 32 + mi * 16 + g + p * 8) * 128);
    #pragma unroll
    for (int ni = 0; ni < 8; ni++)
        bOffB[ni] = (uint32_t)(16384 + (wnn * 64 + ni * 8 + g) * 128);
    #pragma unroll
    for (int s = 0; s < 4; s++)
        coffB[s] = (uint32_t)((((2 * s + (c >> 1)) ^ g) << 4) + (c & 1) * 8);

    for (int i = 0; i < nk; i++) {
        asm volatile("cp.async.wait_group 2;" ::: "memory");
        __syncthreads();
        const uint32_t sb = sbase + (i % 3) * STAGE_BYTES;

        #pragma unroll
        for (int s = 0; s < 4; s++) {
            const uint32_t off = coffB[s];
            uint2 av[2][2];
            #pragma unroll
            for (int mi = 0; mi < 2; mi++) {
                av[mi][0] = lds64(sb + aOffB[mi][0] + off);
                av[mi][1] = lds64(sb + aOffB[mi][1] + off);
            }
            uint2 bv[8];
            #pragma unroll
            for (int ni = 0; ni < 8; ni++)
                bv[ni] = lds64(sb + bOffB[ni] + off);
            #pragma unroll
            for (int mi = 0; mi < 2; mi++)
                #pragma unroll
                for (int ni = 0; ni < 8; ni++)
                    mma8(acc[mi][ni],
                         av[mi][0].x, av[mi][1].x, av[mi][0].y, av[mi][1].y,
                         bv[ni].x, bv[ni].y);
        }
        __syncthreads();

        const int j = i + 3;
        if (j < nk) {
            #pragma unroll
            for (int t = 0; t < 4; t++) {
                asm volatile("cp.async.cg.shared.global [%0], [%1], 16;"
                             :: "r"(sb + soA + t * 4096),
                                "l"(gA + (size_t)(32 * t) * K + j * 32) : "memory");
                asm volatile("cp.async.cg.shared.global [%0], [%1], 16;"
                             :: "r"(sb + 16384 + soA + t * 4096),
                                "l"(gB + (size_t)(32 * t) * K + j * 32) : "memory");
            }
        }
        asm volatile("cp.async.commit_group;" ::: "memory");
    }

    const int p0 = perm8(2 * c);
    const int p1 = perm8(2 * c + 1);
    const bool permStore = (emode == 1 || emode == 3);
    #pragma unroll
    for (int mi = 0; mi < 2; mi++) {
        const int r0 = by * 128 + wm * 32 + mi * 16 + g;
        #pragma unroll
        for (int ni = 0; ni < 8; ni++) {
            const int colg = bx * 128 + wnn * 64 + ni * 8;
            const float bb0 = bias[colg + 2 * c];
            const float bb1 = bias[colg + 2 * c + 1];
            float v00 = acc[mi][ni][0] + bb0;
            float v01 = acc[mi][ni][1] + bb1;
            float v10 = acc[mi][ni][2] + bb0;
            float v11 = acc[mi][ni][3] + bb1;
            if (emode == 1) {
                v00 = gelu_f(v00); v01 = gelu_f(v01);
                v10 = gelu_f(v10); v11 = gelu_f(v11);
            }
            if (emode == 1 || emode == 3 || emode == 4) {
                v00 = rna_tf32(v00); v01 = rna_tf32(v01);
                v10 = rna_tf32(v10); v11 = rna_tf32(v11);
            }
            if (permStore) {
                float* c0 = C + (size_t)r0 * N + colg;
                float* c1 = C + (size_t)(r0 + 8) * N + colg;
                c0[p0] = v00; c0[p1] = v01;
                c1[p0] = v10; c1[p1] = v11;
            } else {
                if (emode == 2) {
                    const float* rr0 = res + (size_t)r0 * N + colg + 2 * c;
                    const float* rr1 = res + (size_t)(r0 + 8) * N + colg + 2 * c;
                    v00 += rr0[0]; v01 += rr0[1];
                    v10 += rr1[0]; v11 += rr1[1];
                }
                float2 o0; o0.x = v00; o0.y = v01;
                float2 o1; o1.x = v10; o1.y = v11;
                *(float2*)(C + (size_t)r0 * N + colg + 2 * c) = o0;
                *(float2*)(C + (size_t)(r0 + 8) * N + colg + 2 * c) = o1;
            }
        }
    }
}

// ---------------- tensor-core flash attention + residual ----------------------
// 64 q-rows per CTA, 4 warps (m16 each). smem: Ks[2][64x64] | Vt[64x64] | P[4][16x64]
#define AKS0 0
#define AKS1 16384
#define AVT  32768
#define AP   49152
#define ATT_SMEM 65536

__global__ __launch_bounds__(128)
void attn_kernel(const float* __restrict__ x, float* __restrict__ x1,
                 float* __restrict__ x1r)
{
    extern __shared__ float sm[];
    const uint32_t sbase = smem_u32(sm);

    const int qt = blockIdx.x, bh = blockIdx.y;
    const int b = bh >> 4, h = bh & 15;
    const int tid = threadIdx.x, lane = tid & 31, w = tid >> 5;
    const int g = lane >> 2, c = lane & 3;

    const size_t headoff = (size_t)b * T * H + (size_t)h * HD;
    const float* Qg = g_q + headoff;
    const float* Kg = g_k + headoff;
    const float* Vg = g_v + headoff;

    // per-thread K/V tile loader mapping: 1024 float4 chunks / 128 threads
    uint32_t kso[8];
    size_t   kgo[8];
    #pragma unroll
    for (int i = 0; i < 8; i++) {
        int f = i * 128 + tid;
        int row = f >> 4;            // 0..63
        int c4  = f & 15;            // float4 index within 64-float row
        kgo[i] = (size_t)row * H + c4 * 4;
        kso[i] = (uint32_t)(row * 256 + (((c4 >> 1) ^ (row & 7)) << 5) + ((c4 & 1) << 4));
    }

    // prologue: cp.async K tile 0 into buf 0
    {
        const float* src = Kg;
        #pragma unroll
        for (int i = 0; i < 8; i++)
            asm volatile("cp.async.cg.shared.global [%0], [%1], 16;"
                         :: "r"(sbase + AKS0 + kso[i]), "l"(src + kgo[i]) : "memory");
        asm volatile("cp.async.commit_group;" ::: "memory");
    }

    // Q A-fragments in registers (gmem q already rounded + d-permuted), scale 1/32
    float qa[8][4];
    {
        const int r0 = qt * 64 + w * 16 + g;
        const float* q0 = Qg + (size_t)r0 * H;
        const float* q1 = Qg + (size_t)(r0 + 8) * H;
        #pragma unroll
        for (int k8 = 0; k8 < 8; k8++) {
            float2 v0 = *(const float2*)(q0 + k8 * 8 + 2 * c);
            float2 v1 = *(const float2*)(q1 + k8 * 8 + 2 * c);
            qa[k8][0] = v0.x * 0.03125f;
            qa[k8][2] = v0.y * 0.03125f;
            qa[k8][1] = v1.x * 0.03125f;
            qa[k8][3] = v1.y * 0.03125f;
        }
    }

    float o[8][4];
    #pragma unroll
    for (int nt = 0; nt < 8; nt++)
        #pragma unroll
        for (int r = 0; r < 4; r++) o[nt][r] = 0.0f;
    float mrow0 = -1e30f, mrow1 = -1e30f, lrow0 = 0.0f, lrow1 = 0.0f;

    const uint32_t vbase = sbase + AVT;
    const uint32_t pbase = sbase + AP + w * 4096;
    const int row0 = w * 16 + g;
    const int pc0 = (c < 2) ? 4 * c : 4 * (c - 2) + 1;   // perm8(2c); perm8(2c+1)=pc0+2
    const int nkt = qt + 1;

    for (int kt = 0; kt < nkt; kt++) {
        const uint32_t kbase = sbase + ((kt & 1) ? AKS1 : AKS0);
        asm volatile("cp.async.wait_group 0;" ::: "memory");
        __syncthreads();

        // V tile LDG into regs (consumed after S-compute)
        float4 vreg[8];
        {
            const float* src = Vg + (size_t)kt * 64 * H;
            #pragma unroll
            for (int i = 0; i < 8; i++)
                vreg[i] = *(const float4*)(src + kgo[i]);
        }
        // prefetch next K tile
        if (kt + 1 < nkt) {
            const float* src = Kg + (size_t)(kt + 1) * 64 * H;
            const uint32_t nb = sbase + ((kt & 1) ? AKS0 : AKS1);
            #pragma unroll
            for (int i = 0; i < 8; i++)
                asm volatile("cp.async.cg.shared.global [%0], [%1], 16;"
                             :: "r"(nb + kso[i]), "l"(src + kgo[i]) : "memory");
            asm volatile("cp.async.commit_group;" ::: "memory");
        }

        // S = Q @ K^T
        float sacc[8][4];
        #pragma unroll
        for (int nt = 0; nt < 8; nt++)
            #pragma unroll
            for (int r = 0; r < 4; r++) sacc[nt][r] = 0.0f;
        #pragma unroll
        for (int k8 = 0; k8 < 8; k8++) {
            const uint32_t ab = kbase + (uint32_t)(((k8 ^ g) << 5) + (c << 3));
            uint2 bf[8];
            #pragma unroll
            for (int nt = 0; nt < 8; nt++)
                bf[nt] = lds64(ab + (uint32_t)((nt * 8 + g) * 256));
            #pragma unroll
            for (int nt = 0; nt < 8; nt++)
                mma8(sacc[nt],
                     __float_as_uint(qa[k8][0]), __float_as_uint(qa[k8][1]),
                     __float_as_uint(qa[k8][2]), __float_as_uint(qa[k8][3]),
                     bf[nt].x, bf[nt].y);
        }

        // mask (diag tile) + online softmax
        if (kt == qt) {
            #pragma unroll
            for (int nt = 0; nt < 8; nt++) {
                const int colb = nt * 8 + 2 * c;
                if (colb     > row0)     sacc[nt][0] = -1e30f;
                if (colb + 1 > row0)     sacc[nt][1] = -1e30f;
                if (colb     > row0 + 8) sacc[nt][2] = -1e30f;
                if (colb + 1 > row0 + 8) sacc[nt][3] = -1e30f;
            }
        }
        float mx0 = -1e30f, mx1 = -1e30f;
        #pragma unroll
        for (int nt = 0; nt < 8; nt++) {
            mx0 = fmaxf(mx0, fmaxf(sacc[nt][0], sacc[nt][1]));
            mx1 = fmaxf(mx1, fmaxf(sacc[nt][2], sacc[nt][3]));
        }
        mx0 = fmaxf(mx0, __shfl_xor_sync(0xffffffffu, mx0, 1));
        mx0 = fmaxf(mx0, __shfl_xor_sync(0xffffffffu, mx0, 2));
        mx1 = fmaxf(mx1, __shfl_xor_sync(0xffffffffu, mx1, 1));
        mx1 = fmaxf(mx1, __shfl_xor_sync(0xffffffffu, mx1, 2));
        const float mn0 = fmaxf(mrow0, mx0);
        const float mn1 = fmaxf(mrow1, mx1);
        const float al0 = __expf(mrow0 - mn0);
        const float al1 = __expf(mrow1 - mn1);
        mrow0 = mn0; mrow1 = mn1;

        float rs0 = 0.0f, rs1 = 0.0f;
        #pragma unroll
        for (int nt = 0; nt < 8; nt++) {
            float p00 = __expf(sacc[nt][0] - mn0);
            float p01 = __expf(sacc[nt][1] - mn0);
            float p10 = __expf(sacc[nt][2] - mn1);
            float p11 = __expf(sacc[nt][3] - mn1);
            rs0 += p00 + p01;
            rs1 += p10 + p11;
            const uint32_t a0 = pbase + (uint32_t)(g * 256 + ((nt ^ g) << 5) + pc0 * 4);
            sm[(a0 - sbase) >> 2]        = rna_tf32(p00);
            sm[((a0 + 8) - sbase) >> 2]  = rna_tf32(p01);
            sm[((a0 + 2048) - sbase) >> 2]        = rna_tf32(p10);
            sm[((a0 + 2048 + 8) - sbase) >> 2]    = rna_tf32(p11);
        }
        rs0 += __shfl_xor_sync(0xffffffffu, rs0, 1);
        rs0 += __shfl_xor_sync(0xffffffffu, rs0, 2);
        rs1 += __shfl_xor_sync(0xffffffffu, rs1, 1);
        rs1 += __shfl_xor_sync(0xffffffffu, rs1, 2);
        lrow0 = lrow0 * al0 + rs0;
        lrow1 = lrow1 * al1 + rs1;
        #pragma unroll
        for (int nt = 0; nt < 8; nt++) {
            o[nt][0] *= al0; o[nt][1] *= al0;
            o[nt][2] *= al1; o[nt][3] *= al1;
        }
        __syncwarp();

        // V regs -> Vt smem (transposed, key-permuted, swizzled, rounded)
        #pragma unroll
        for (int i = 0; i < 8; i++) {
            const int f = i * 128 + tid;
            const int key = f >> 4;
            const int c4  = f & 15;
            const uint32_t base = vbase + (uint32_t)(perm8(key & 7) * 4);
            const float vv[4] = {vreg[i].x, vreg[i].y, vreg[i].z, vreg[i].w};
            #pragma unroll
            for (int j = 0; j < 4; j++) {
                const int d = c4 * 4 + j;
                const uint32_t ad = base + (uint32_t)(d * 256 + (((key >> 3) ^ (d & 7)) << 5));
                sm[(ad - sbase) >> 2] = rna_tf32(vv[j]);
            }
        }
        __syncthreads();

        // O += P @ V
        #pragma unroll
        for (int k8 = 0; k8 < 8; k8++) {
            const uint32_t off = (uint32_t)(((k8 ^ g) << 5) + (c << 3));
            const uint2 pa0 = lds64(pbase + (uint32_t)(g * 256) + off);
            const uint2 pa1 = lds64(pbase + (uint32_t)(g * 256 + 2048) + off);
            #pragma unroll
            for (int nt = 0; nt < 8; nt++) {
                const uint2 vb = lds64(vbase + (uint32_t)((nt * 8 + g) * 256) + off);
                mma8(o[nt], pa0.x, pa1.x, pa0.y, pa1.y, vb.x, vb.y);
            }
        }
        __syncthreads();
    }

    // epilogue: x1 = x + O/l (exact), x1r = rna+perm
    const float inv0 = 1.0f / lrow0;
    const float inv1 = 1.0f / lrow1;
    const int r0 = qt * 64 + w * 16 + g;
    const size_t rb0 = (size_t)b * T * H + (size_t)r0 * H + (size_t)h * HD;
    const size_t rb1 = rb0 + 8 * H;
    #pragma unroll
    for (int nt = 0; nt < 8; nt++) {
        const int d0 = nt * 8 + 2 * c;
        float v00 = o[nt][0] * inv0 + x[rb0 + d0];
        float v01 = o[nt][1] * inv0 + x[rb0 + d0 + 1];
        float v10 = o[nt][2] * inv1 + x[rb1 + d0];
        float v11 = o[nt][3] * inv1 + x[rb1 + d0 + 1];
        float2 t0; t0.x = v00; t0.y = v01;
        float2 t1; t1.x = v10; t1.y = v11;
        *(float2*)(x1 + rb0 + d0) = t0;
        *(float2*)(x1 + rb1 + d0) = t1;
        const size_t gb0 = rb0 + nt * 8;
        const size_t gb1 = rb1 + nt * 8;
        x1r[gb0 + pc0]     = rna_tf32(v00);
        x1r[gb0 + pc0 + 2] = rna_tf32(v01);
        x1r[gb1 + pc0]     = rna_tf32(v10);
        x1r[gb1 + pc0 + 2] = rna_tf32(v11);
    }
}

// ---------------- launch -----------------------------------------------------
extern "C" void kernel_launch(void* const* d_in, const int* in_sizes, int n_in,
                              void* d_out, int out_size)
{
    const float* x  = (const float*)d_in[0];
    const float* Wq = (const float*)d_in[1];
    const float* bq = (const float*)d_in[2];
    const float* Wk = (const float*)d_in[3];
    const float* bk = (const float*)d_in[4];
    const float* Wv = (const float*)d_in[5];
    const float* bv = (const float*)d_in[6];
    const float* W1 = (const float*)d_in[7];
    const float* b1 = (const float*)d_in[8];
    const float* W2 = (const float*)d_in[9];
    const float* b2 = (const float*)d_in[10];
    float* out = (float*)d_out;

    float *q, *k, *v, *x1, *x1r, *xr, *h, *wqt, *wkt, *wvt, *w1t, *w2t;
    cudaGetSymbolAddress((void**)&q,    g_q);
    cudaGetSymbolAddress((void**)&k,    g_k);
    cudaGetSymbolAddress((void**)&v,    g_v);
    cudaGetSymbolAddress((void**)&x1,   g_x1);
    cudaGetSymbolAddress((void**)&x1r,  g_x1r);
    cudaGetSymbolAddress((void**)&xr,   g_xr);
    cudaGetSymbolAddress((void**)&h,    g_h);
    cudaGetSymbolAddress((void**)&wqt,  g_wqt);
    cudaGetSymbolAddress((void**)&wkt,  g_wkt);
    cudaGetSymbolAddress((void**)&wvt,  g_wvt);
    cudaGetSymbolAddress((void**)&w1t,  g_w1t);
    cudaGetSymbolAddress((void**)&w2t,  g_w2t);

    round_perm_k<<<(BT * H) / (256 * 8), 256>>>(x, xr, BT * H);
    dim3 tb(32, 8);
    transpose_rna_perm_k<<<dim3(H / 32,  H / 32),  tb>>>(Wq, wqt, H, H);
    transpose_rna_perm_k<<<dim3(H / 32,  H / 32),  tb>>>(Wk, wkt, H, H);
    transpose_rna_perm_k<<<dim3(H / 32,  H / 32),  tb>>>(Wv, wvt, H, H);
    transpose_rna_perm_k<<<dim3(FF / 32, H / 32),  tb>>>(W1, w1t, H, FF);
    transpose_rna_perm_k<<<dim3(H / 32,  FF / 32), tb>>>(W2, w2t, FF, H);

    cudaFuncSetAttribute(gemm_tf32, cudaFuncAttributeMaxDynamicSharedMemorySize, GEMM_SMEM);

    // QKV (q,k: rounded+permuted; v: rounded)
    gemm_tf32<<<dim3(H / 128, BT / 128, 3), 256, GEMM_SMEM>>>(
        xr, wqt, wkt, wvt, bq, bk, bv, q, k, v, nullptr, H, H, 3);

    cudaFuncSetAttribute(attn_kernel, cudaFuncAttributeMaxDynamicSharedMemorySize, ATT_SMEM);
    attn_kernel<<<dim3(T / 64, BATCH * NHEAD), 128, ATT_SMEM>>>(x, x1, x1r);

    // MLP1
    gemm_tf32<<<dim3(FF / 128, BT / 128, 1), 256, GEMM_SMEM>>>(
        x1r, w1t, w1t, w1t, b1, b1, b1, h, h, h, nullptr, H, FF, 1);

    // MLP2
    gemm_tf32<<<dim3(H / 128, BT / 128, 1), 256, GEMM_SMEM>>>(
        h, w2t, w2t, w2t, b2, b2, b2, out, out, out, x1, FF, H, 2);
}

// round 5
// speedup vs baseline: 1.6389x; 1.6389x over previous
#include <cuda_runtime.h>
#include <math.h>
#include <stdint.h>

#define BATCH 4
#define T 2048
#define H 1024
#define NHEAD 16
#define HD 64
#define FF 4096
#define BT (BATCH * T)   // 8192 rows

// ---------------- scratch (allocation-free: __device__ globals) --------------
__device__ float g_q[BT * H];      // tf32-rounded, d-permuted
__device__ float g_k[BT * H];      // tf32-rounded, d-permuted
__device__ float g_vt[BT * H];     // V^T: [b][h][d][T], tf32-rounded, key-permuted
__device__ float g_x1[BT * H];     // x + attn_out (exact)
__device__ float g_x1r[BT * H];    // tf32-rounded, k-permuted x1
__device__ float g_xr[BT * H];     // tf32-rounded, k-permuted x
__device__ float g_h[BT * FF];     // tf32-rounded, k-permuted gelu(x1@W1+b1)
__device__ float g_wqt[H * H];     // transposed + rounded + k-permuted weights [N,K]
__device__ float g_wkt[H * H];
__device__ float g_wvt[H * H];
__device__ float g_w1t[H * FF];    // [FF, H]
__device__ float g_w2t[FF * H];    // [H, FF]

// ---------------- helpers ----------------------------------------------------
__device__ __forceinline__ uint32_t smem_u32(const void* p) {
    uint32_t a;
    asm("{ .reg .u64 t; cvta.to.shared.u64 t, %1; cvt.u32.u64 %0, t; }"
        : "=r"(a) : "l"(p));
    return a;
}
__device__ __forceinline__ float rna_tf32(float x) {
    uint32_t u;
    asm("cvt.rna.tf32.f32 %0, %1;" : "=r"(u) : "f"(x));
    return __uint_as_float(u);
}
__device__ __forceinline__ float ftanh(float x) {
    float y;
    asm("tanh.approx.f32 %0, %1;" : "=f"(y) : "f"(x));
    return y;
}
__device__ __forceinline__ float gelu_f(float x) {
    return 0.5f * x * (1.0f + ftanh(0.7978845608028654f * (x + 0.044715f * x * x * x)));
}
// physical position of logical k-index l within its 8-group: [k0,k4,k1,k5,k2,k6,k3,k7]
__device__ __forceinline__ int perm8(int l) {
    return (l < 4) ? (2 * l) : (2 * (l - 4) + 1);
}
__device__ __forceinline__ uint2 lds64(uint32_t addr) {
    uint2 v;
    asm volatile("ld.shared.v2.b32 {%0, %1}, [%2];" : "=r"(v.x), "=r"(v.y) : "r"(addr));
    return v;
}
__device__ __forceinline__ void mma8(float* d, uint32_t a0, uint32_t a1, uint32_t a2,
                                     uint32_t a3, uint32_t b0, uint32_t b1) {
    asm volatile(
        "mma.sync.aligned.m16n8k8.row.col.f32.tf32.tf32.f32 "
        "{%0,%1,%2,%3}, {%4,%5,%6,%7}, {%8,%9}, {%0,%1,%2,%3};"
        : "+f"(d[0]), "+f"(d[1]), "+f"(d[2]), "+f"(d[3])
        : "r"(a0), "r"(a1), "r"(a2), "r"(a3), "r"(b0), "r"(b1));
}

// ---------------- prep kernels ------------------------------------------------
__global__ void round_perm_k(const float* __restrict__ in, float* __restrict__ out, int n) {
    int i = (blockIdx.x * blockDim.x + threadIdx.x) * 8;
    if (i < n) {
        float4 lo = *(const float4*)(in + i);
        float4 hi = *(const float4*)(in + i + 4);
        float4 o0, o1;
        o0.x = rna_tf32(lo.x); o0.y = rna_tf32(hi.x);
        o0.z = rna_tf32(lo.y); o0.w = rna_tf32(hi.y);
        o1.x = rna_tf32(lo.z); o1.y = rna_tf32(hi.z);
        o1.z = rna_tf32(lo.w); o1.w = rna_tf32(hi.w);
        *(float4*)(out + i)     = o0;
        *(float4*)(out + i + 4) = o1;
    }
}

__global__ void transpose_rna_perm_k(const float* __restrict__ W, float* __restrict__ Wt,
                                     int K, int N) {
    __shared__ float t[32][33];
    int n0 = blockIdx.x * 32, k0 = blockIdx.y * 32;
    int tx = threadIdx.x, ty = threadIdx.y;
    #pragma unroll
    for (int j = ty; j < 32; j += 8)
        t[j][tx] = W[(size_t)(k0 + j) * N + n0 + tx];
    __syncthreads();
    int kk = k0 + tx;
    int kphys = (kk & ~7) + perm8(kk & 7);
    #pragma unroll
    for (int j = ty; j < 32; j += 8)
        Wt[(size_t)(n0 + j) * K + kphys] = rna_tf32(t[tx][j]);
}

// ---------------- tf32 mma.sync GEMM ------------------------------------------
// modes: 0 plain, 1 gelu+rna+perm, 2 +res, 3 rna+perm (q/k; z==2 -> emode 4: V^T)
#define STAGE_BYTES 32768
#define GEMM_SMEM   (3 * STAGE_BYTES)

__global__ __launch_bounds__(256, 2)
void gemm_tf32(const float* __restrict__ A,
               const float* __restrict__ B0t, const float* __restrict__ B1t,
               const float* __restrict__ B2t,
               const float* __restrict__ bias0, const float* __restrict__ bias1,
               const float* __restrict__ bias2,
               float* __restrict__ C0, float* __restrict__ C1, float* __restrict__ C2,
               const float* __restrict__ res, float* __restrict__ vt,
               int K, int N, int mode)
{
    extern __shared__ float sf[];
    const uint32_t sbase = smem_u32(sf);

    const float* Bt = B0t; const float* bias = bias0; float* C = C0;
    if (blockIdx.z == 1) { Bt = B1t; bias = bias1; C = C1; }
    else if (blockIdx.z == 2) { Bt = B2t; bias = bias2; C = C2; }
    int emode = mode;
    if (mode == 3 && blockIdx.z == 2) emode = 4;

    const int tid  = threadIdx.x;
    const int lane = tid & 31;
    const int w    = tid >> 5;
    const int g    = lane >> 2;
    const int c    = lane & 3;
    const int wm   = w & 3;
    const int wnn  = w >> 2;
    const int bx = blockIdx.x, by = blockIdx.y;
    const int nk = K >> 5;

    const int rowl = tid >> 3;
    const int cj   = tid & 7;
    const uint32_t soA = (uint32_t)(rowl * 128 + ((cj ^ (rowl & 7)) << 4));
    const float* gA = A  + (size_t)(by * 128 + rowl) * K + cj * 4;
    const float* gB = Bt + (size_t)(bx * 128 + rowl) * K + cj * 4;

    #pragma unroll
    for (int s = 0; s < 3; s++) {
        uint32_t sb = sbase + s * STAGE_BYTES;
        #pragma unroll
        for (int t = 0; t < 4; t++) {
            asm volatile("cp.async.cg.shared.global [%0], [%1], 16;"
                         :: "r"(sb + soA + t * 4096),
                            "l"(gA + (size_t)(32 * t) * K + s * 32) : "memory");
            asm volatile("cp.async.cg.shared.global [%0], [%1], 16;"
                         :: "r"(sb + 16384 + soA + t * 4096),
                            "l"(gB + (size_t)(32 * t) * K + s * 32) : "memory");
        }
        asm volatile("cp.async.commit_group;" ::: "memory");
    }

    float acc[2][8][4];
    #pragma unroll
    for (int mi = 0; mi < 2; mi++)
        #pragma unroll
        for (int ni = 0; ni < 8; ni++)
            #pragma unroll
            for (int r = 0; r < 4; r++) acc[mi][ni][r] = 0.0f;

    uint32_t aOffB[2][2], bOffB[8], coffB[4];
    #pragma unroll
    for (int mi = 0; mi < 2; mi++)
        #pragma unroll
        for (int p = 0; p < 2; p++)
            aOffB[mi][p] = (uint32_t)((wm * 32 + mi * 16 + g + p * 8) * 128);
    #pragma unroll
    for (int ni = 0; ni < 8; ni++)
        bOffB[ni] = (uint32_t)(16384 + (wnn * 64 + ni * 8 + g) * 128);
    #pragma unroll
    for (int s = 0; s < 4; s++)
        coffB[s] = (uint32_t)((((2 * s + (c >> 1)) ^ g) << 4) + (c & 1) * 8);

    for (int i = 0; i < nk; i++) {
        asm volatile("cp.async.wait_group 2;" ::: "memory");
        __syncthreads();
        const uint32_t sb = sbase + (i % 3) * STAGE_BYTES;

        #pragma unroll
        for (int s = 0; s < 4; s++) {
            const uint32_t off = coffB[s];
            uint2 av[2][2];
            #pragma unroll
            for (int mi = 0; mi < 2; mi++) {
                av[mi][0] = lds64(sb + aOffB[mi][0] + off);
                av[mi][1] = lds64(sb + aOffB[mi][1] + off);
            }
            uint2 bv[8];
            #pragma unroll
            for (int ni = 0; ni < 8; ni++)
                bv[ni] = lds64(sb + bOffB[ni] + off);
            #pragma unroll
            for (int mi = 0; mi < 2; mi++)
                #pragma unroll
                for (int ni = 0; ni < 8; ni++)
                    mma8(acc[mi][ni],
                         av[mi][0].x, av[mi][1].x, av[mi][0].y, av[mi][1].y,
                         bv[ni].x, bv[ni].y);
        }
        __syncthreads();

        const int j = i + 3;
        if (j < nk) {
            #pragma unroll
            for (int t = 0; t < 4; t++) {
                asm volatile("cp.async.cg.shared.global [%0], [%1], 16;"
                             :: "r"(sb + soA + t * 4096),
                                "l"(gA + (size_t)(32 * t) * K + j * 32) : "memory");
                asm volatile("cp.async.cg.shared.global [%0], [%1], 16;"
                             :: "r"(sb + 16384 + soA + t * 4096),
                                "l"(gB + (size_t)(32 * t) * K + j * 32) : "memory");
            }
        }
        asm volatile("cp.async.commit_group;" ::: "memory");
    }

    const int p0 = perm8(2 * c);
    const int p1 = perm8(2 * c + 1);
    const int perm8g = perm8(g);
    const bool permStore = (emode == 1 || emode == 3);
    #pragma unroll
    for (int mi = 0; mi < 2; mi++) {
        const int r0 = by * 128 + wm * 32 + mi * 16 + g;
        #pragma unroll
        for (int ni = 0; ni < 8; ni++) {
            const int colg = bx * 128 + wnn * 64 + ni * 8;
            const float bb0 = bias[colg + 2 * c];
            const float bb1 = bias[colg + 2 * c + 1];
            float v00 = acc[mi][ni][0] + bb0;
            float v01 = acc[mi][ni][1] + bb1;
            float v10 = acc[mi][ni][2] + bb0;
            float v11 = acc[mi][ni][3] + bb1;
            if (emode == 1) {
                v00 = gelu_f(v00); v01 = gelu_f(v01);
                v10 = gelu_f(v10); v11 = gelu_f(v11);
            }
            if (emode == 1 || emode == 3 || emode == 4) {
                v00 = rna_tf32(v00); v01 = rna_tf32(v01);
                v10 = rna_tf32(v10); v11 = rna_tf32(v11);
            }
            if (emode == 4) {
                // V^T store: [b][h][d][T] with key (token) permuted within 8-groups
                const int col0 = colg + 2 * c;             // channel
                const int b0   = r0 >> 11;                 // token block
                const int tb   = (r0 & 2047) & ~7;         // token base (g == r0&7)
                float* vb = vt + ((size_t)(b0 * 16 + (col0 >> 6)) * 64 + (col0 & 63)) * 2048
                               + tb + perm8g;
                vb[0]        = v00;
                vb[2048]     = v01;
                vb[8]        = v10;
                vb[2048 + 8] = v11;
            } else if (permStore) {
                float* c0 = C + (size_t)r0 * N + colg;
                float* c1 = C + (size_t)(r0 + 8) * N + colg;
                c0[p0] = v00; c0[p1] = v01;
                c1[p0] = v10; c1[p1] = v11;
            } else {
                if (emode == 2) {
                    const float* rr0 = res + (size_t)r0 * N + colg + 2 * c;
                    const float* rr1 = res + (size_t)(r0 + 8) * N + colg + 2 * c;
                    v00 += rr0[0]; v01 += rr0[1];
                    v10 += rr1[0]; v11 += rr1[1];
                }
                float2 o0; o0.x = v00; o0.y = v01;
                float2 o1; o1.x = v10; o1.y = v11;
                *(float2*)(C + (size_t)r0 * N + colg + 2 * c) = o0;
                *(float2*)(C + (size_t)(r0 + 8) * N + colg + 2 * c) = o1;
            }
        }
    }
}

// ---------------- tensor-core flash attention + residual ----------------------
// 128 q-rows per CTA, 8 warps (m16 each). K and V^T double-buffered.
// smem: K[2][64x64] | VT[2][64x64] | P[8][16x64]  = 96KB
#define AVT0 32768
#define AP   65536
#define ATT_SMEM 98304

__global__ __launch_bounds__(256, 2)
void attn_kernel(const float* __restrict__ x, float* __restrict__ x1,
                 float* __restrict__ x1r)
{
    extern __shared__ float sm[];
    const uint32_t sbase = smem_u32(sm);

    const int qt = blockIdx.x, bh = blockIdx.y;
    const int b = bh >> 4, h = bh & 15;
    const int tid = threadIdx.x, lane = tid & 31, w = tid >> 5;
    const int g = lane >> 2, c = lane & 3;

    const size_t headoff = (size_t)b * T * H + (size_t)h * HD;
    const float* Qg  = g_q + headoff;
    const float* Kg  = g_k + headoff;
    const float* VTg = g_vt + (size_t)bh * HD * T;

    // tile loader: 1024 16B chunks per tile, 256 threads -> 4 chunks each (K and VT)
    const int lrow = tid >> 2;            // 0..63
    const int lc4x = (tid & 3) << 2;      // base float4 index {0,4,8,12}
    const float* kgp  = Kg  + (size_t)lrow * H + lc4x * 4;
    const float* vtgp = VTg + (size_t)lrow * T + lc4x * 4;
    uint32_t lso[4];
    #pragma unroll
    for (int i = 0; i < 4; i++) {
        int c4 = lc4x + i;
        lso[i] = (uint32_t)(lrow * 256 + ((((c4 >> 1) ^ (lrow & 7)) << 5)) + ((c4 & 1) << 4));
    }

    const int nkt = 2 * qt + 2;

    // prologue: load tile 0 (K + VT)
    #pragma unroll
    for (int i = 0; i < 4; i++) {
        asm volatile("cp.async.cg.shared.global [%0], [%1], 16;"
                     :: "r"(sbase + lso[i]), "l"(kgp + i * 4) : "memory");
        asm volatile("cp.async.cg.shared.global [%0], [%1], 16;"
                     :: "r"(sbase + AVT0 + lso[i]), "l"(vtgp + i * 4) : "memory");
    }
    asm volatile("cp.async.commit_group;" ::: "memory");

    // Q fragments in registers (q is rounded + d-permuted), pre-scaled by 1/32
    float qa[8][4];
    {
        const int r0 = qt * 128 + w * 16 + g;
        const float* q0 = Qg + (size_t)r0 * H;
        const float* q1 = q0 + 8 * H;
        #pragma unroll
        for (int k8 = 0; k8 < 8; k8++) {
            float2 v0 = *(const float2*)(q0 + k8 * 8 + 2 * c);
            float2 v1 = *(const float2*)(q1 + k8 * 8 + 2 * c);
            qa[k8][0] = v0.x * 0.03125f;
            qa[k8][2] = v0.y * 0.03125f;
            qa[k8][1] = v1.x * 0.03125f;
            qa[k8][3] = v1.y * 0.03125f;
        }
    }

    float o[8][4];
    #pragma unroll
    for (int nt = 0; nt < 8; nt++)
        #pragma unroll
        for (int r = 0; r < 4; r++) o[nt][r] = 0.0f;
    float mrow0 = -1e30f, mrow1 = -1e30f, lrow0 = 0.0f, lrow1 = 0.0f;

    const uint32_t pbase = sbase + AP + w * 4096;
    const int rowlo = qt * 128 + w * 16;
    const int row0 = rowlo + g;
    const int pc0 = (c < 2) ? 4 * c : 4 * (c - 2) + 1;   // perm8(2c); perm8(2c+1)=pc0+2

    for (int kt = 0; kt < nkt; kt++) {
        const uint32_t buf = (kt & 1) ? 16384u : 0u;
        asm volatile("cp.async.wait_group 0;" ::: "memory");
        __syncthreads();

        // prefetch next tile
        if (kt + 1 < nkt) {
            const uint32_t nb = (kt & 1) ? 0u : 16384u;
            const float* ks = kgp  + (size_t)(kt + 1) * 64 * H;
            const float* vs = vtgp + (kt + 1) * 64;
            #pragma unroll
            for (int i = 0; i < 4; i++) {
                asm volatile("cp.async.cg.shared.global [%0], [%1], 16;"
                             :: "r"(sbase + nb + lso[i]), "l"(ks + i * 4) : "memory");
                asm volatile("cp.async.cg.shared.global [%0], [%1], 16;"
                             :: "r"(sbase + AVT0 + nb + lso[i]), "l"(vs + i * 4) : "memory");
            }
        }
        asm volatile("cp.async.commit_group;" ::: "memory");

        const int ktbase = kt * 64;
        const bool active = (ktbase <= rowlo + 15);
        if (active) {
            const uint32_t kbuf  = sbase + buf;
            const uint32_t vtbuf = sbase + AVT0 + buf;

            // S = Q @ K^T
            float sacc[8][4];
            #pragma unroll
            for (int nt = 0; nt < 8; nt++)
                #pragma unroll
                for (int r = 0; r < 4; r++) sacc[nt][r] = 0.0f;
            #pragma unroll
            for (int k8 = 0; k8 < 8; k8++) {
                const uint32_t ab = kbuf + (uint32_t)(((k8 ^ g) << 5) + (c << 3));
                uint2 bf[8];
                #pragma unroll
                for (int nt = 0; nt < 8; nt++)
                    bf[nt] = lds64(ab + (uint32_t)((nt * 8 + g) * 256));
                #pragma unroll
                for (int nt = 0; nt < 8; nt++)
                    mma8(sacc[nt],
                         __float_as_uint(qa[k8][0]), __float_as_uint(qa[k8][1]),
                         __float_as_uint(qa[k8][2]), __float_as_uint(qa[k8][3]),
                         bf[nt].x, bf[nt].y);
            }

            // causal mask (only needed near the diagonal)
            if (ktbase + 63 > rowlo) {
                #pragma unroll
                for (int nt = 0; nt < 8; nt++) {
                    const int colb = ktbase + nt * 8 + 2 * c;
                    if (colb     > row0)     sacc[nt][0] = -1e30f;
                    if (colb + 1 > row0)     sacc[nt][1] = -1e30f;
                    if (colb     > row0 + 8) sacc[nt][2] = -1e30f;
                    if (colb + 1 > row0 + 8) sacc[nt][3] = -1e30f;
                }
            }

            // online softmax
            float mx0 = -1e30f, mx1 = -1e30f;
            #pragma unroll
            for (int nt = 0; nt < 8; nt++) {
                mx0 = fmaxf(mx0, fmaxf(sacc[nt][0], sacc[nt][1]));
                mx1 = fmaxf(mx1, fmaxf(sacc[nt][2], sacc[nt][3]));
            }
            mx0 = fmaxf(mx0, __shfl_xor_sync(0xffffffffu, mx0, 1));
            mx0 = fmaxf(mx0, __shfl_xor_sync(0xffffffffu, mx0, 2));
            mx1 = fmaxf(mx1, __shfl_xor_sync(0xffffffffu, mx1, 1));
            mx1 = fmaxf(mx1, __shfl_xor_sync(0xffffffffu, mx1, 2));
            const float mn0 = fmaxf(mrow0, mx0);
            const float mn1 = fmaxf(mrow1, mx1);
            const float al0 = __expf(mrow0 - mn0);
            const float al1 = __expf(mrow1 - mn1);
            mrow0 = mn0; mrow1 = mn1;

            float rs0 = 0.0f, rs1 = 0.0f;
            #pragma unroll
            for (int nt = 0; nt < 8; nt++) {
                float p00 = __expf(sacc[nt][0] - mn0);
                float p01 = __expf(sacc[nt][1] - mn0);
                float p10 = __expf(sacc[nt][2] - mn1);
                float p11 = __expf(sacc[nt][3] - mn1);
                rs0 += p00 + p01;
                rs1 += p10 + p11;
                const uint32_t a0 = pbase + (uint32_t)(g * 256 + ((nt ^ g) << 5) + pc0 * 4);
                sm[(a0 - sbase) >> 2]              = rna_tf32(p00);
                sm[((a0 + 8) - sbase) >> 2]        = rna_tf32(p01);
                sm[((a0 + 2048) - sbase) >> 2]     = rna_tf32(p10);
                sm[((a0 + 2048 + 8) - sbase) >> 2] = rna_tf32(p11);
            }
            rs0 += __shfl_xor_sync(0xffffffffu, rs0, 1);
            rs0 += __shfl_xor_sync(0xffffffffu, rs0, 2);
            rs1 += __shfl_xor_sync(0xffffffffu, rs1, 1);
            rs1 += __shfl_xor_sync(0xffffffffu, rs1, 2);
            lrow0 = lrow0 * al0 + rs0;
            lrow1 = lrow1 * al1 + rs1;
            #pragma unroll
            for (int nt = 0; nt < 8; nt++) {
                o[nt][0] *= al0; o[nt][1] *= al0;
                o[nt][2] *= al1; o[nt][3] *= al1;
            }
            __syncwarp();

            // O += P @ V  (V^T tile already transposed + permuted in smem)
            #pragma unroll
            for (int k8 = 0; k8 < 8; k8++) {
                const uint32_t off = (uint32_t)(((k8 ^ g) << 5) + (c << 3));
                const uint2 pa0 = lds64(pbase + (uint32_t)(g * 256) + off);
                const uint2 pa1 = lds64(pbase + (uint32_t)(g * 256 + 2048) + off);
                #pragma unroll
                for (int nt = 0; nt < 8; nt++) {
                    const uint2 vb = lds64(vtbuf + (uint32_t)((nt * 8 + g) * 256) + off);
                    mma8(o[nt], pa0.x, pa1.x, pa0.y, pa1.y, vb.x, vb.y);
                }
            }
        }
    }

    // epilogue: x1 = x + O/l (exact), x1r = rna + k-perm
    const float inv0 = 1.0f / lrow0;
    const float inv1 = 1.0f / lrow1;
    const size_t rb0 = (size_t)b * T * H + (size_t)row0 * H + (size_t)h * HD;
    const size_t rb1 = rb0 + 8 * H;
    #pragma unroll
    for (int nt = 0; nt < 8; nt++) {
        const int d0 = nt * 8 + 2 * c;
        float v00 = o[nt][0] * inv0 + x[rb0 + d0];
        float v01 = o[nt][1] * inv0 + x[rb0 + d0 + 1];
        float v10 = o[nt][2] * inv1 + x[rb1 + d0];
        float v11 = o[nt][3] * inv1 + x[rb1 + d0 + 1];
        float2 t0; t0.x = v00; t0.y = v01;
        float2 t1; t1.x = v10; t1.y = v11;
        *(float2*)(x1 + rb0 + d0) = t0;
        *(float2*)(x1 + rb1 + d0) = t1;
        const size_t gb0 = rb0 + nt * 8;
        const size_t gb1 = rb1 + nt * 8;
        x1r[gb0 + pc0]     = rna_tf32(v00);
        x1r[gb0 + pc0 + 2] = rna_tf32(v01);
        x1r[gb1 + pc0]     = rna_tf32(v10);
        x1r[gb1 + pc0 + 2] = rna_tf32(v11);
    }
}

// ---------------- launch -----------------------------------------------------
extern "C" void kernel_launch(void* const* d_in, const int* in_sizes, int n_in,
                              void* d_out, int out_size)
{
    const float* x  = (const float*)d_in[0];
    const float* Wq = (const float*)d_in[1];
    const float* bq = (const float*)d_in[2];
    const float* Wk = (const float*)d_in[3];
    const float* bk = (const float*)d_in[4];
    const float* Wv = (const float*)d_in[5];
    const float* bv = (const float*)d_in[6];
    const float* W1 = (const float*)d_in[7];
    const float* b1 = (const float*)d_in[8];
    const float* W2 = (const float*)d_in[9];
    const float* b2 = (const float*)d_in[10];
    float* out = (float*)d_out;

    float *q, *k, *vt, *x1, *x1r, *xr, *h, *wqt, *wkt, *wvt, *w1t, *w2t;
    cudaGetSymbolAddress((void**)&q,    g_q);
    cudaGetSymbolAddress((void**)&k,    g_k);
    cudaGetSymbolAddress((void**)&vt,   g_vt);
    cudaGetSymbolAddress((void**)&x1,   g_x1);
    cudaGetSymbolAddress((void**)&x1r,  g_x1r);
    cudaGetSymbolAddress((void**)&xr,   g_xr);
    cudaGetSymbolAddress((void**)&h,    g_h);
    cudaGetSymbolAddress((void**)&wqt,  g_wqt);
    cudaGetSymbolAddress((void**)&wkt,  g_wkt);
    cudaGetSymbolAddress((void**)&wvt,  g_wvt);
    cudaGetSymbolAddress((void**)&w1t,  g_w1t);
    cudaGetSymbolAddress((void**)&w2t,  g_w2t);

    round_perm_k<<<(BT * H) / (256 * 8), 256>>>(x, xr, BT * H);
    dim3 tb(32, 8);
    transpose_rna_perm_k<<<dim3(H / 32,  H / 32),  tb>>>(Wq, wqt, H, H);
    transpose_rna_perm_k<<<dim3(H / 32,  H / 32),  tb>>>(Wk, wkt, H, H);
    transpose_rna_perm_k<<<dim3(H / 32,  H / 32),  tb>>>(Wv, wvt, H, H);
    transpose_rna_perm_k<<<dim3(FF / 32, H / 32),  tb>>>(W1, w1t, H, FF);
    transpose_rna_perm_k<<<dim3(H / 32,  FF / 32), tb>>>(W2, w2t, FF, H);

    cudaFuncSetAttribute(gemm_tf32, cudaFuncAttributeMaxDynamicSharedMemorySize, GEMM_SMEM);

    // QKV (q,k: rounded + d-permuted; v: rounded -> V^T layout)
    gemm_tf32<<<dim3(H / 128, BT / 128, 3), 256, GEMM_SMEM>>>(
        xr, wqt, wkt, wvt, bq, bk, bv, q, k, nullptr, nullptr, vt, H, H, 3);

    cudaFuncSetAttribute(attn_kernel, cudaFuncAttributeMaxDynamicSharedMemorySize, ATT_SMEM);
    attn_kernel<<<dim3(T / 128, BATCH * NHEAD), 256, ATT_SMEM>>>(x, x1, x1r);

    // MLP1
    gemm_tf32<<<dim3(FF / 128, BT / 128, 1), 256, GEMM_SMEM>>>(
        x1r, w1t, w1t, w1t, b1, b1, b1, h, h, h, nullptr, nullptr, H, FF, 1);

    // MLP2
    gemm_tf32<<<dim3(H / 128, BT / 128, 1), 256, GEMM_SMEM>>>(
        h, w2t, w2t, w2t, b2, b2, b2, out, out, out, x1, nullptr, FF, H, 2);
}

// round 6
// speedup vs baseline: 1.9813x; 1.2089x over previous
#include <cuda_runtime.h>
#include <math.h>
#include <stdint.h>

#define BATCH 4
#define T 2048
#define H 1024
#define NHEAD 16
#define HD 64
#define FF 4096
#define BT (BATCH * T)   // 8192 rows

// ---------------- scratch (allocation-free: __device__ globals) --------------
__device__ float g_q[BT * H];      // tf32-rounded, d-permuted
__device__ float g_k[BT * H];      // tf32-rounded, d-permuted
__device__ float g_vt[BT * H];     // V^T: [b][h][d][T], tf32-rounded, key-permuted
__device__ float g_x1[BT * H];     // x + attn_out (exact)
__device__ float g_x1r[BT * H];    // tf32-rounded, k-permuted x1
__device__ float g_xr[BT * H];     // tf32-rounded, k-permuted x
__device__ float g_h[BT * FF];     // tf32-rounded, k-permuted gelu(x1@W1+b1)
__device__ float g_wqt[H * H];     // transposed + rounded + k-permuted weights [N,K]
__device__ float g_wkt[H * H];
__device__ float g_wvt[H * H];
__device__ float g_w1t[H * FF];    // [FF, H]
__device__ float g_w2t[FF * H];    // [H, FF]

// ---------------- helpers ----------------------------------------------------
__device__ __forceinline__ uint32_t smem_u32(const void* p) {
    uint32_t a;
    asm("{ .reg .u64 t; cvta.to.shared.u64 t, %1; cvt.u32.u64 %0, t; }"
        : "=r"(a) : "l"(p));
    return a;
}
__device__ __forceinline__ float rna_tf32(float x) {
    uint32_t u;
    asm("cvt.rna.tf32.f32 %0, %1;" : "=r"(u) : "f"(x));
    return __uint_as_float(u);
}
__device__ __forceinline__ float ftanh(float x) {
    float y;
    asm("tanh.approx.f32 %0, %1;" : "=f"(y) : "f"(x));
    return y;
}
__device__ __forceinline__ float gelu_f(float x) {
    return 0.5f * x * (1.0f + ftanh(0.7978845608028654f * (x + 0.044715f * x * x * x)));
}
// physical position of logical k-index l within its 8-group: [k0,k4,k1,k5,k2,k6,k3,k7]
__device__ __forceinline__ int perm8(int l) {
    return (l < 4) ? (2 * l) : (2 * (l - 4) + 1);
}
__device__ __forceinline__ uint2 lds64(uint32_t addr) {
    uint2 v;
    asm volatile("ld.shared.v2.b32 {%0, %1}, [%2];" : "=r"(v.x), "=r"(v.y) : "r"(addr));
    return v;
}
__device__ __forceinline__ void mma8(float* d, uint32_t a0, uint32_t a1, uint32_t a2,
                                     uint32_t a3, uint32_t b0, uint32_t b1) {
    asm volatile(
        "mma.sync.aligned.m16n8k8.row.col.f32.tf32.tf32.f32 "
        "{%0,%1,%2,%3}, {%4,%5,%6,%7}, {%8,%9}, {%0,%1,%2,%3};"
        : "+f"(d[0]), "+f"(d[1]), "+f"(d[2]), "+f"(d[3])
        : "r"(a0), "r"(a1), "r"(a2), "r"(a3), "r"(b0), "r"(b1));
}

// ---------------- prep kernels ------------------------------------------------
__global__ void round_perm_k(const float* __restrict__ in, float* __restrict__ out, int n) {
    int i = (blockIdx.x * blockDim.x + threadIdx.x) * 8;
    if (i < n) {
        float4 lo = *(const float4*)(in + i);
        float4 hi = *(const float4*)(in + i + 4);
        float4 o0, o1;
        o0.x = rna_tf32(lo.x); o0.y = rna_tf32(hi.x);
        o0.z = rna_tf32(lo.y); o0.w = rna_tf32(hi.y);
        o1.x = rna_tf32(lo.z); o1.y = rna_tf32(hi.z);
        o1.z = rna_tf32(lo.w); o1.w = rna_tf32(hi.w);
        *(float4*)(out + i)     = o0;
        *(float4*)(out + i + 4) = o1;
    }
}

// all five weight transposes in ONE launch (keeps total launch count at 6)
__global__ void transpose_all(const float* __restrict__ Wq, const float* __restrict__ Wk,
                              const float* __restrict__ Wv, const float* __restrict__ W1,
                              const float* __restrict__ W2,
                              float* __restrict__ wqt, float* __restrict__ wkt,
                              float* __restrict__ wvt, float* __restrict__ w1t,
                              float* __restrict__ w2t)
{
    __shared__ float t[32][33];
    const int bid = blockIdx.x;
    const float* W; float* Wt; int K, N, tile;
    if (bid < 1024)      { W = Wq; Wt = wqt; K = H;  N = H;  tile = bid; }
    else if (bid < 2048) { W = Wk; Wt = wkt; K = H;  N = H;  tile = bid - 1024; }
    else if (bid < 3072) { W = Wv; Wt = wvt; K = H;  N = H;  tile = bid - 2048; }
    else if (bid < 7168) { W = W1; Wt = w1t; K = H;  N = FF; tile = bid - 3072; }
    else                 { W = W2; Wt = w2t; K = FF; N = H;  tile = bid - 7168; }
    const int ntx = N >> 5;
    const int n0 = (tile % ntx) * 32, k0 = (tile / ntx) * 32;
    const int tx = threadIdx.x, ty = threadIdx.y;
    #pragma unroll
    for (int j = ty; j < 32; j += 8)
        t[j][tx] = W[(size_t)(k0 + j) * N + n0 + tx];
    __syncthreads();
    const int kk = k0 + tx;
    const int kphys = (kk & ~7) + perm8(kk & 7);
    #pragma unroll
    for (int j = ty; j < 32; j += 8)
        Wt[(size_t)(n0 + j) * K + kphys] = rna_tf32(t[tx][j]);
}

// ---------------- tf32 mma.sync GEMM ------------------------------------------
// C[M, 256-tile] = A[M,Kperm] @ Bt[N,Kperm]^T. CTA tile 128x256, warp tile 64x64.
// 4 stages (48KB each), lookahead 3, ONE __syncthreads per iter.
// modes: 0 plain, 1 gelu+rna+perm, 2 +res, 3 rna+perm (q/k; z==2 -> emode 4: V^T)
#define STAGE_BYTES 49152                 // 16KB A + 32KB B
#define GEMM_SMEM   (4 * STAGE_BYTES)     // 196608

__global__ __launch_bounds__(256, 1)
void gemm_tf32(const float* __restrict__ A,
               const float* __restrict__ B0t, const float* __restrict__ B1t,
               const float* __restrict__ B2t,
               const float* __restrict__ bias0, const float* __restrict__ bias1,
               const float* __restrict__ bias2,
               float* __restrict__ C0, float* __restrict__ C1, float* __restrict__ C2,
               const float* __restrict__ res, float* __restrict__ vt,
               int K, int N, int mode)
{
    extern __shared__ float sf[];
    const uint32_t sbase = smem_u32(sf);

    const float* Bt = B0t; const float* bias = bias0; float* C = C0;
    if (blockIdx.z == 1) { Bt = B1t; bias = bias1; C = C1; }
    else if (blockIdx.z == 2) { Bt = B2t; bias = bias2; C = C2; }
    int emode = mode;
    if (mode == 3 && blockIdx.z == 2) emode = 4;

    const int tid  = threadIdx.x;
    const int lane = tid & 31;
    const int w    = tid >> 5;
    const int g    = lane >> 2;
    const int c    = lane & 3;
    const int wm   = w & 1;          // M half (64 rows)
    const int wn   = w >> 1;         // N quarter (64 cols)
    const int bx = blockIdx.x, by = blockIdx.y;
    const int nk = K >> 5;

    // loader: A rows lrow+32t (t<4), B rows lrow+32u (u<8), fixed 16B chunk cj
    const int lrow = tid >> 3;
    const int cj   = tid & 7;
    const uint32_t sA = (uint32_t)(lrow * 128 + ((cj ^ (lrow & 7)) << 4));
    const float* gA = A  + (size_t)(by * 128 + lrow) * K + cj * 4;
    const float* gB = Bt + (size_t)(bx * 256 + lrow) * K + cj * 4;

    #pragma unroll
    for (int s = 0; s < 3; s++) {
        const uint32_t sb = sbase + s * STAGE_BYTES;
        #pragma unroll
        for (int t = 0; t < 4; t++)
            asm volatile("cp.async.cg.shared.global [%0], [%1], 16;"
                         :: "r"(sb + sA + t * 4096),
                            "l"(gA + (size_t)(32 * t) * K + s * 32) : "memory");
        #pragma unroll
        for (int u = 0; u < 8; u++)
            asm volatile("cp.async.cg.shared.global [%0], [%1], 16;"
                         :: "r"(sb + 16384 + sA + u * 4096),
                            "l"(gB + (size_t)(32 * u) * K + s * 32) : "memory");
        asm volatile("cp.async.commit_group;" ::: "memory");
    }

    float acc[4][8][4];
    #pragma unroll
    for (int mi = 0; mi < 4; mi++)
        #pragma unroll
        for (int ni = 0; ni < 8; ni++)
            #pragma unroll
            for (int r = 0; r < 4; r++) acc[mi][ni][r] = 0.0f;

    const uint32_t abase = (uint32_t)((wm * 64 + g) * 128);
    const uint32_t bbase = (uint32_t)(16384 + (wn * 64 + g) * 128);
    uint32_t coff[4];
    #pragma unroll
    for (int s = 0; s < 4; s++)
        coff[s] = (uint32_t)((((2 * s + (c >> 1)) ^ g) << 4) + (c & 1) * 8);

    for (int i = 0; i < nk; i++) {
        asm volatile("cp.async.wait_group 2;" ::: "memory");
        __syncthreads();
        const uint32_t sb = sbase + (i & 3) * STAGE_BYTES;

        #pragma unroll
        for (int s = 0; s < 4; s++) {
            const uint32_t off = coff[s];
            uint2 av[4][2];
            #pragma unroll
            for (int mi = 0; mi < 4; mi++) {
                av[mi][0] = lds64(sb + abase + mi * 2048 + off);
                av[mi][1] = lds64(sb + abase + mi * 2048 + 1024 + off);
            }
            uint2 bv[8];
            #pragma unroll
            for (int ni = 0; ni < 8; ni++)
                bv[ni] = lds64(sb + bbase + ni * 1024 + off);
            #pragma unroll
            for (int mi = 0; mi < 4; mi++)
                #pragma unroll
                for (int ni = 0; ni < 8; ni++)
                    mma8(acc[mi][ni],
                         av[mi][0].x, av[mi][1].x, av[mi][0].y, av[mi][1].y,
                         bv[ni].x, bv[ni].y);
        }

        const int j = i + 3;
        if (j < nk) {
            const uint32_t sb2 = sbase + (j & 3) * STAGE_BYTES;
            #pragma unroll
            for (int t = 0; t < 4; t++)
                asm volatile("cp.async.cg.shared.global [%0], [%1], 16;"
                             :: "r"(sb2 + sA + t * 4096),
                                "l"(gA + (size_t)(32 * t) * K + j * 32) : "memory");
            #pragma unroll
            for (int u = 0; u < 8; u++)
                asm volatile("cp.async.cg.shared.global [%0], [%1], 16;"
                             :: "r"(sb2 + 16384 + sA + u * 4096),
                                "l"(gB + (size_t)(32 * u) * K + j * 32) : "memory");
        }
        asm volatile("cp.async.commit_group;" ::: "memory");
    }

    // ---- epilogue ----
    const int p0 = perm8(2 * c);
    const int p1 = perm8(2 * c + 1);
    const int perm8g = perm8(g);
    const bool permStore = (emode == 1 || emode == 3);
    #pragma unroll
    for (int mi = 0; mi < 4; mi++) {
        const int r0 = by * 128 + wm * 64 + mi * 16 + g;
        #pragma unroll
        for (int ni = 0; ni < 8; ni++) {
            const int colg = bx * 256 + wn * 64 + ni * 8;
            const float bb0 = bias[colg + 2 * c];
            const float bb1 = bias[colg + 2 * c + 1];
            float v00 = acc[mi][ni][0] + bb0;
            float v01 = acc[mi][ni][1] + bb1;
            float v10 = acc[mi][ni][2] + bb0;
            float v11 = acc[mi][ni][3] + bb1;
            if (emode == 1) {
                v00 = gelu_f(v00); v01 = gelu_f(v01);
                v10 = gelu_f(v10); v11 = gelu_f(v11);
            }
            if (emode == 1 || emode == 3 || emode == 4) {
                v00 = rna_tf32(v00); v01 = rna_tf32(v01);
                v10 = rna_tf32(v10); v11 = rna_tf32(v11);
            }
            if (emode == 4) {
                // V^T store: [b][h][d][T], token (key) permuted within 8-groups
                const int col0 = colg + 2 * c;
                const int b0   = r0 >> 11;
                const int tb   = (r0 & 2047) & ~7;
                float* vb = vt + ((size_t)(b0 * 16 + (col0 >> 6)) * 64 + (col0 & 63)) * 2048
                               + tb + perm8g;
                vb[0]        = v00;
                vb[2048]     = v01;
                vb[8]        = v10;
                vb[2048 + 8] = v11;
            } else if (permStore) {
                float* c0 = C + (size_t)r0 * N + colg;
                float* c1 = C + (size_t)(r0 + 8) * N + colg;
                c0[p0] = v00; c0[p1] = v01;
                c1[p0] = v10; c1[p1] = v11;
            } else {
                if (emode == 2) {
                    const float* rr0 = res + (size_t)r0 * N + colg + 2 * c;
                    const float* rr1 = res + (size_t)(r0 + 8) * N + colg + 2 * c;
                    v00 += rr0[0]; v01 += rr0[1];
                    v10 += rr1[0]; v11 += rr1[1];
                }
                float2 o0; o0.x = v00; o0.y = v01;
                float2 o1; o1.x = v10; o1.y = v11;
                *(float2*)(C + (size_t)r0 * N + colg + 2 * c) = o0;
                *(float2*)(C + (size_t)(r0 + 8) * N + colg + 2 * c) = o1;
            }
        }
    }
}

// ---------------- tensor-core flash attention + residual ----------------------
// 128 q-rows per CTA, 8 warps (m16 each). K and V^T double-buffered.
// smem: K[2][64x64] | VT[2][64x64] | P[8][16x64]  = 96KB
#define AVT0 32768
#define AP   65536
#define ATT_SMEM 98304

__global__ __launch_bounds__(256, 2)
void attn_kernel(const float* __restrict__ x, float* __restrict__ x1,
                 float* __restrict__ x1r)
{
    extern __shared__ float sm[];
    const uint32_t sbase = smem_u32(sm);

    const int qt = blockIdx.x, bh = blockIdx.y;
    const int b = bh >> 4, h = bh & 15;
    const int tid = threadIdx.x, lane = tid & 31, w = tid >> 5;
    const int g = lane >> 2, c = lane & 3;

    const size_t headoff = (size_t)b * T * H + (size_t)h * HD;
    const float* Qg  = g_q + headoff;
    const float* Kg  = g_k + headoff;
    const float* VTg = g_vt + (size_t)bh * HD * T;

    const int lrow = tid >> 2;            // 0..63
    const int lc4x = (tid & 3) << 2;      // base float4 index {0,4,8,12}
    const float* kgp  = Kg  + (size_t)lrow * H + lc4x * 4;
    const float* vtgp = VTg + (size_t)lrow * T + lc4x * 4;
    uint32_t lso[4];
    #pragma unroll
    for (int i = 0; i < 4; i++) {
        int c4 = lc4x + i;
        lso[i] = (uint32_t)(lrow * 256 + ((((c4 >> 1) ^ (lrow & 7)) << 5)) + ((c4 & 1) << 4));
    }

    const int nkt = 2 * qt + 2;

    #pragma unroll
    for (int i = 0; i < 4; i++) {
        asm volatile("cp.async.cg.shared.global [%0], [%1], 16;"
                     :: "r"(sbase + lso[i]), "l"(kgp + i * 4) : "memory");
        asm volatile("cp.async.cg.shared.global [%0], [%1], 16;"
                     :: "r"(sbase + AVT0 + lso[i]), "l"(vtgp + i * 4) : "memory");
    }
    asm volatile("cp.async.commit_group;" ::: "memory");

    float qa[8][4];
    {
        const int r0 = qt * 128 + w * 16 + g;
        const float* q0 = Qg + (size_t)r0 * H;
        const float* q1 = q0 + 8 * H;
        #pragma unroll
        for (int k8 = 0; k8 < 8; k8++) {
            float2 v0 = *(const float2*)(q0 + k8 * 8 + 2 * c);
            float2 v1 = *(const float2*)(q1 + k8 * 8 + 2 * c);
            qa[k8][0] = v0.x * 0.03125f;
            qa[k8][2] = v0.y * 0.03125f;
            qa[k8][1] = v1.x * 0.03125f;
            qa[k8][3] = v1.y * 0.03125f;
        }
    }

    float o[8][4];
    #pragma unroll
    for (int nt = 0; nt < 8; nt++)
        #pragma unroll
        for (int r = 0; r < 4; r++) o[nt][r] = 0.0f;
    float mrow0 = -1e30f, mrow1 = -1e30f, lrow0 = 0.0f, lrow1 = 0.0f;

    const uint32_t pbase = sbase + AP + w * 4096;
    const int rowlo = qt * 128 + w * 16;
    const int row0 = rowlo + g;
    const int pc0 = (c < 2) ? 4 * c : 4 * (c - 2) + 1;

    for (int kt = 0; kt < nkt; kt++) {
        const uint32_t buf = (kt & 1) ? 16384u : 0u;
        asm volatile("cp.async.wait_group 0;" ::: "memory");
        __syncthreads();

        if (kt + 1 < nkt) {
            const uint32_t nb = (kt & 1) ? 0u : 16384u;
            const float* ks = kgp  + (size_t)(kt + 1) * 64 * H;
            const float* vs = vtgp + (kt + 1) * 64;
            #pragma unroll
            for (int i = 0; i < 4; i++) {
                asm volatile("cp.async.cg.shared.global [%0], [%1], 16;"
                             :: "r"(sbase + nb + lso[i]), "l"(ks + i * 4) : "memory");
                asm volatile("cp.async.cg.shared.global [%0], [%1], 16;"
                             :: "r"(sbase + AVT0 + nb + lso[i]), "l"(vs + i * 4) : "memory");
            }
        }
        asm volatile("cp.async.commit_group;" ::: "memory");

        const int ktbase = kt * 64;
        const bool active = (ktbase <= rowlo + 15);
        if (active) {
            const uint32_t kbuf  = sbase + buf;
            const uint32_t vtbuf = sbase + AVT0 + buf;

            float sacc[8][4];
            #pragma unroll
            for (int nt = 0; nt < 8; nt++)
                #pragma unroll
                for (int r = 0; r < 4; r++) sacc[nt][r] = 0.0f;
            #pragma unroll
            for (int k8 = 0; k8 < 8; k8++) {
                const uint32_t ab = kbuf + (uint32_t)(((k8 ^ g) << 5) + (c << 3));
                uint2 bf[8];
                #pragma unroll
                for (int nt = 0; nt < 8; nt++)
                    bf[nt] = lds64(ab + (uint32_t)((nt * 8 + g) * 256));
                #pragma unroll
                for (int nt = 0; nt < 8; nt++)
                    mma8(sacc[nt],
                         __float_as_uint(qa[k8][0]), __float_as_uint(qa[k8][1]),
                         __float_as_uint(qa[k8][2]), __float_as_uint(qa[k8][3]),
                         bf[nt].x, bf[nt].y);
            }

            if (ktbase + 63 > rowlo) {
                #pragma unroll
                for (int nt = 0; nt < 8; nt++) {
                    const int colb = ktbase + nt * 8 + 2 * c;
                    if (colb     > row0)     sacc[nt][0] = -1e30f;
                    if (colb + 1 > row0)     sacc[nt][1] = -1e30f;
                    if (colb     > row0 + 8) sacc[nt][2] = -1e30f;
                    if (colb + 1 > row0 + 8) sacc[nt][3] = -1e30f;
                }
            }

            float mx0 = -1e30f, mx1 = -1e30f;
            #pragma unroll
            for (int nt = 0; nt < 8; nt++) {
                mx0 = fmaxf(mx0, fmaxf(sacc[nt][0], sacc[nt][1]));
                mx1 = fmaxf(mx1, fmaxf(sacc[nt][2], sacc[nt][3]));
            }
            mx0 = fmaxf(mx0, __shfl_xor_sync(0xffffffffu, mx0, 1));
            mx0 = fmaxf(mx0, __shfl_xor_sync(0xffffffffu, mx0, 2));
            mx1 = fmaxf(mx1, __shfl_xor_sync(0xffffffffu, mx1, 1));
            mx1 = fmaxf(mx1, __shfl_xor_sync(0xffffffffu, mx1, 2));
            const float mn0 = fmaxf(mrow0, mx0);
            const float mn1 = fmaxf(mrow1, mx1);
            const float al0 = __expf(mrow0 - mn0);
            const float al1 = __expf(mrow1 - mn1);
            mrow0 = mn0; mrow1 = mn1;

            float rs0 = 0.0f, rs1 = 0.0f;
            #pragma unroll
            for (int nt = 0; nt < 8; nt++) {
                float p00 = __expf(sacc[nt][0] - mn0);
                float p01 = __expf(sacc[nt][1] - mn0);
                float p10 = __expf(sacc[nt][2] - mn1);
                float p11 = __expf(sacc[nt][3] - mn1);
                rs0 += p00 + p01;
                rs1 += p10 + p11;
                const uint32_t a0 = pbase + (uint32_t)(g * 256 + ((nt ^ g) << 5) + pc0 * 4);
                sm[(a0 - sbase) >> 2]              = rna_tf32(p00);
                sm[((a0 + 8) - sbase) >> 2]        = rna_tf32(p01);
                sm[((a0 + 2048) - sbase) >> 2]     = rna_tf32(p10);
                sm[((a0 + 2048 + 8) - sbase) >> 2] = rna_tf32(p11);
            }
            rs0 += __shfl_xor_sync(0xffffffffu, rs0, 1);
            rs0 += __shfl_xor_sync(0xffffffffu, rs0, 2);
            rs1 += __shfl_xor_sync(0xffffffffu, rs1, 1);
            rs1 += __shfl_xor_sync(0xffffffffu, rs1, 2);
            lrow0 = lrow0 * al0 + rs0;
            lrow1 = lrow1 * al1 + rs1;
            #pragma unroll
            for (int nt = 0; nt < 8; nt++) {
                o[nt][0] *= al0; o[nt][1] *= al0;
                o[nt][2] *= al1; o[nt][3] *= al1;
            }
            __syncwarp();

            #pragma unroll
            for (int k8 = 0; k8 < 8; k8++) {
                const uint32_t off = (uint32_t)(((k8 ^ g) << 5) + (c << 3));
                const uint2 pa0 = lds64(pbase + (uint32_t)(g * 256) + off);
                const uint2 pa1 = lds64(pbase + (uint32_t)(g * 256 + 2048) + off);
                #pragma unroll
                for (int nt = 0; nt < 8; nt++) {
                    const uint2 vb = lds64(vtbuf + (uint32_t)((nt * 8 + g) * 256) + off);
                    mma8(o[nt], pa0.x, pa1.x, pa0.y, pa1.y, vb.x, vb.y);
                }
            }
        }
    }

    const float inv0 = 1.0f / lrow0;
    const float inv1 = 1.0f / lrow1;
    const size_t rb0 = (size_t)b * T * H + (size_t)row0 * H + (size_t)h * HD;
    const size_t rb1 = rb0 + 8 * H;
    #pragma unroll
    for (int nt = 0; nt < 8; nt++) {
        const int d0 = nt * 8 + 2 * c;
        float v00 = o[nt][0] * inv0 + x[rb0 + d0];
        float v01 = o[nt][1] * inv0 + x[rb0 + d0 + 1];
        float v10 = o[nt][2] * inv1 + x[rb1 + d0];
        float v11 = o[nt][3] * inv1 + x[rb1 + d0 + 1];
        float2 t0; t0.x = v00; t0.y = v01;
        float2 t1; t1.x = v10; t1.y = v11;
        *(float2*)(x1 + rb0 + d0) = t0;
        *(float2*)(x1 + rb1 + d0) = t1;
        const size_t gb0 = rb0 + nt * 8;
        const size_t gb1 = rb1 + nt * 8;
        x1r[gb0 + pc0]     = rna_tf32(v00);
        x1r[gb0 + pc0 + 2] = rna_tf32(v01);
        x1r[gb1 + pc0]     = rna_tf32(v10);
        x1r[gb1 + pc0 + 2] = rna_tf32(v11);
    }
}

// ---------------- launch -----------------------------------------------------
extern "C" void kernel_launch(void* const* d_in, const int* in_sizes, int n_in,
                              void* d_out, int out_size)
{
    const float* x  = (const float*)d_in[0];
    const float* Wq = (const float*)d_in[1];
    const float* bq = (const float*)d_in[2];
    const float* Wk = (const float*)d_in[3];
    const float* bk = (const float*)d_in[4];
    const float* Wv = (const float*)d_in[5];
    const float* bv = (const float*)d_in[6];
    const float* W1 = (const float*)d_in[7];
    const float* b1 = (const float*)d_in[8];
    const float* W2 = (const float*)d_in[9];
    const float* b2 = (const float*)d_in[10];
    float* out = (float*)d_out;

    float *q, *k, *vt, *x1, *x1r, *xr, *h, *wqt, *wkt, *wvt, *w1t, *w2t;
    cudaGetSymbolAddress((void**)&q,    g_q);
    cudaGetSymbolAddress((void**)&k,    g_k);
    cudaGetSymbolAddress((void**)&vt,   g_vt);
    cudaGetSymbolAddress((void**)&x1,   g_x1);
    cudaGetSymbolAddress((void**)&x1r,  g_x1r);
    cudaGetSymbolAddress((void**)&xr,   g_xr);
    cudaGetSymbolAddress((void**)&h,    g_h);
    cudaGetSymbolAddress((void**)&wqt,  g_wqt);
    cudaGetSymbolAddress((void**)&wkt,  g_wkt);
    cudaGetSymbolAddress((void**)&wvt,  g_wvt);
    cudaGetSymbolAddress((void**)&w1t,  g_w1t);
    cudaGetSymbolAddress((void**)&w2t,  g_w2t);

    round_perm_k<<<(BT * H) / (256 * 8), 256>>>(x, xr, BT * H);
    transpose_all<<<11264, dim3(32, 8)>>>(Wq, Wk, Wv, W1, W2, wqt, wkt, wvt, w1t, w2t);

    cudaFuncSetAttribute(gemm_tf32, cudaFuncAttributeMaxDynamicSharedMemorySize, GEMM_SMEM);

    // QKV (q,k: rounded + d-permuted; v: rounded -> V^T layout)
    gemm_tf32<<<dim3(H / 256, BT / 128, 3), 256, GEMM_SMEM>>>(
        xr, wqt, wkt, wvt, bq, bk, bv, q, k, nullptr, nullptr, vt, H, H, 3);

    cudaFuncSetAttribute(attn_kernel, cudaFuncAttributeMaxDynamicSharedMemorySize, ATT_SMEM);
    attn_kernel<<<dim3(T / 128, BATCH * NHEAD), 256, ATT_SMEM>>>(x, x1, x1r);

    // MLP1
    gemm_tf32<<<dim3(FF / 256, BT / 128, 1), 256, GEMM_SMEM>>>(
        x1r, w1t, w1t, w1t, b1, b1, b1, h, h, h, nullptr, nullptr, H, FF, 1);

    // MLP2
    gemm_tf32<<<dim3(H / 256, BT / 128, 1), 256, GEMM_SMEM>>>(
        h, w2t, w2t, w2t, b2, b2, b2, out, out, out, x1, nullptr, FF, H, 2);
}

// round 7
// speedup vs baseline: 2.1451x; 1.0827x over previous
#include <cuda_runtime.h>
#include <math.h>
#include <stdint.h>

#define BATCH 4
#define T 2048
#define H 1024
#define NHEAD 16
#define HD 64
#define FF 4096
#define BT (BATCH * T)   // 8192 rows

// ---------------- scratch (allocation-free: __device__ globals) --------------
__device__ float g_q[BT * H];      // tf32-rounded, d-permuted
__device__ float g_k[BT * H];      // tf32-rounded, d-permuted
__device__ float g_vt[BT * H];     // V^T: [b][h][d][T], tf32-rounded, key-permuted
__device__ float g_x1[BT * H];     // x + attn_out (exact)
__device__ float g_x1r[BT * H];    // tf32-rounded, k-permuted x1
__device__ float g_xr[BT * H];     // tf32-rounded, k-permuted x
__device__ float g_h[BT * FF];     // tf32-rounded, k-permuted gelu(x1@W1+b1)
__device__ float g_wqt[H * H];     // transposed + rounded + k-permuted weights [N,K]
__device__ float g_wkt[H * H];
__device__ float g_wvt[H * H];
__device__ float g_w1t[H * FF];    // [FF, H]
__device__ float g_w2t[FF * H];    // [H, FF]

// ---------------- helpers ----------------------------------------------------
__device__ __forceinline__ uint32_t smem_u32(const void* p) {
    uint32_t a;
    asm("{ .reg .u64 t; cvta.to.shared.u64 t, %1; cvt.u32.u64 %0, t; }"
        : "=r"(a) : "l"(p));
    return a;
}
__device__ __forceinline__ float rna_tf32(float x) {
    uint32_t u;
    asm("cvt.rna.tf32.f32 %0, %1;" : "=r"(u) : "f"(x));
    return __uint_as_float(u);
}
__device__ __forceinline__ float ftanh(float x) {
    float y;
    asm("tanh.approx.f32 %0, %1;" : "=f"(y) : "f"(x));
    return y;
}
__device__ __forceinline__ float gelu_f(float x) {
    return 0.5f * x * (1.0f + ftanh(0.7978845608028654f * (x + 0.044715f * x * x * x)));
}
// physical position of logical k-index l within its 8-group: [k0,k4,k1,k5,k2,k6,k3,k7]
__device__ __forceinline__ int perm8(int l) {
    return (l < 4) ? (2 * l) : (2 * (l - 4) + 1);
}
__device__ __forceinline__ uint2 lds64(uint32_t addr) {
    uint2 v;
    asm volatile("ld.shared.v2.b32 {%0, %1}, [%2];" : "=r"(v.x), "=r"(v.y) : "r"(addr));
    return v;
}
__device__ __forceinline__ void mma8(float* d, uint32_t a0, uint32_t a1, uint32_t a2,
                                     uint32_t a3, uint32_t b0, uint32_t b1) {
    asm volatile(
        "mma.sync.aligned.m16n8k8.row.col.f32.tf32.tf32.f32 "
        "{%0,%1,%2,%3}, {%4,%5,%6,%7}, {%8,%9}, {%0,%1,%2,%3};"
        : "+f"(d[0]), "+f"(d[1]), "+f"(d[2]), "+f"(d[3])
        : "r"(a0), "r"(a1), "r"(a2), "r"(a3), "r"(b0), "r"(b1));
}

// ---------------- prep kernels ------------------------------------------------
__global__ void round_perm_k(const float* __restrict__ in, float* __restrict__ out, int n) {
    int i = (blockIdx.x * blockDim.x + threadIdx.x) * 8;
    if (i < n) {
        float4 lo = *(const float4*)(in + i);
        float4 hi = *(const float4*)(in + i + 4);
        float4 o0, o1;
        o0.x = rna_tf32(lo.x); o0.y = rna_tf32(hi.x);
        o0.z = rna_tf32(lo.y); o0.w = rna_tf32(hi.y);
        o1.x = rna_tf32(lo.z); o1.y = rna_tf32(hi.z);
        o1.z = rna_tf32(lo.w); o1.w = rna_tf32(hi.w);
        *(float4*)(out + i)     = o0;
        *(float4*)(out + i + 4) = o1;
    }
}

// all five weight transposes in ONE launch
__global__ void transpose_all(const float* __restrict__ Wq, const float* __restrict__ Wk,
                              const float* __restrict__ Wv, const float* __restrict__ W1,
                              const float* __restrict__ W2,
                              float* __restrict__ wqt, float* __restrict__ wkt,
                              float* __restrict__ wvt, float* __restrict__ w1t,
                              float* __restrict__ w2t)
{
    __shared__ float t[32][33];
    const int bid = blockIdx.x;
    const float* W; float* Wt; int K, N, tile;
    if (bid < 1024)      { W = Wq; Wt = wqt; K = H;  N = H;  tile = bid; }
    else if (bid < 2048) { W = Wk; Wt = wkt; K = H;  N = H;  tile = bid - 1024; }
    else if (bid < 3072) { W = Wv; Wt = wvt; K = H;  N = H;  tile = bid - 2048; }
    else if (bid < 7168) { W = W1; Wt = w1t; K = H;  N = FF; tile = bid - 3072; }
    else                 { W = W2; Wt = w2t; K = FF; N = H;  tile = bid - 7168; }
    const int ntx = N >> 5;
    const int n0 = (tile % ntx) * 32, k0 = (tile / ntx) * 32;
    const int tx = threadIdx.x, ty = threadIdx.y;
    #pragma unroll
    for (int j = ty; j < 32; j += 8)
        t[j][tx] = W[(size_t)(k0 + j) * N + n0 + tx];
    __syncthreads();
    const int kk = k0 + tx;
    const int kphys = (kk & ~7) + perm8(kk & 7);
    #pragma unroll
    for (int j = ty; j < 32; j += 8)
        Wt[(size_t)(n0 + j) * K + kphys] = rna_tf32(t[tx][j]);
}

// ---------------- tf32 mma.sync GEMM ------------------------------------------
// C[M, 256-tile] = A[M,Kperm] @ Bt[N,Kperm]^T. CTA tile 128x256, warp tile 64x64.
// 4 stages (48KB each), lookahead 3, ONE __syncthreads per iter.
// Swizzle: chunk ^ ((row&3)<<1) -> fragment LDS.64 conflict-free in both phases.
// modes: 0 plain, 1 gelu+rna+perm, 2 +res, 3 rna+perm (q/k; z==2 -> emode 4: V^T)
#define STAGE_BYTES 49152                 // 16KB A + 32KB B
#define GEMM_SMEM   (4 * STAGE_BYTES)     // 196608

__global__ __launch_bounds__(256, 1)
void gemm_tf32(const float* __restrict__ A,
               const float* __restrict__ B0t, const float* __restrict__ B1t,
               const float* __restrict__ B2t,
               const float* __restrict__ bias0, const float* __restrict__ bias1,
               const float* __restrict__ bias2,
               float* __restrict__ C0, float* __restrict__ C1, float* __restrict__ C2,
               const float* __restrict__ res, float* __restrict__ vt,
               int K, int N, int mode)
{
    extern __shared__ float sf[];
    const uint32_t sbase = smem_u32(sf);

    const float* Bt = B0t; const float* bias = bias0; float* C = C0;
    if (blockIdx.z == 1) { Bt = B1t; bias = bias1; C = C1; }
    else if (blockIdx.z == 2) { Bt = B2t; bias = bias2; C = C2; }
    int emode = mode;
    if (mode == 3 && blockIdx.z == 2) emode = 4;

    const int tid  = threadIdx.x;
    const int lane = tid & 31;
    const int w    = tid >> 5;
    const int g    = lane >> 2;
    const int c    = lane & 3;
    const int wm   = w & 1;          // M half (64 rows)
    const int wn   = w >> 1;         // N quarter (64 cols)
    const int bx = blockIdx.x, by = blockIdx.y;
    const int nk = K >> 5;

    // loader: A rows lrow+32t (t<4), B rows lrow+32u (u<8), fixed 16B chunk cj
    const int lrow = tid >> 3;
    const int cj   = tid & 7;
    const uint32_t sA = (uint32_t)(lrow * 128 + ((cj ^ ((lrow & 3) << 1)) << 4));
    const float* gA = A  + (size_t)(by * 128 + lrow) * K + cj * 4;
    const float* gB = Bt + (size_t)(bx * 256 + lrow) * K + cj * 4;

    #pragma unroll
    for (int s = 0; s < 3; s++) {
        const uint32_t sb = sbase + s * STAGE_BYTES;
        #pragma unroll
        for (int t = 0; t < 4; t++)
            asm volatile("cp.async.cg.shared.global [%0], [%1], 16;"
                         :: "r"(sb + sA + t * 4096),
                            "l"(gA + (size_t)(32 * t) * K + s * 32) : "memory");
        #pragma unroll
        for (int u = 0; u < 8; u++)
            asm volatile("cp.async.cg.shared.global [%0], [%1], 16;"
                         :: "r"(sb + 16384 + sA + u * 4096),
                            "l"(gB + (size_t)(32 * u) * K + s * 32) : "memory");
        asm volatile("cp.async.commit_group;" ::: "memory");
    }

    float acc[4][8][4];
    #pragma unroll
    for (int mi = 0; mi < 4; mi++)
        #pragma unroll
        for (int ni = 0; ni < 8; ni++)
            #pragma unroll
            for (int r = 0; r < 4; r++) acc[mi][ni][r] = 0.0f;

    const uint32_t abase = (uint32_t)((wm * 64 + g) * 128);
    const uint32_t bbase = (uint32_t)(16384 + (wn * 64 + g) * 128);
    uint32_t coff[4];
    #pragma unroll
    for (int s = 0; s < 4; s++)
        coff[s] = (uint32_t)((((2 * s + (c >> 1)) ^ ((g & 3) << 1)) << 4) + (c & 1) * 8);

    for (int i = 0; i < nk; i++) {
        asm volatile("cp.async.wait_group 2;" ::: "memory");
        __syncthreads();
        const uint32_t sb = sbase + (i & 3) * STAGE_BYTES;

        #pragma unroll
        for (int s = 0; s < 4; s++) {
            const uint32_t off = coff[s];
            uint2 av[4][2];
            #pragma unroll
            for (int mi = 0; mi < 4; mi++) {
                av[mi][0] = lds64(sb + abase + mi * 2048 + off);
                av[mi][1] = lds64(sb + abase + mi * 2048 + 1024 + off);
            }
            uint2 bv[8];
            #pragma unroll
            for (int ni = 0; ni < 8; ni++)
                bv[ni] = lds64(sb + bbase + ni * 1024 + off);
            #pragma unroll
            for (int mi = 0; mi < 4; mi++)
                #pragma unroll
                for (int ni = 0; ni < 8; ni++)
                    mma8(acc[mi][ni],
                         av[mi][0].x, av[mi][1].x, av[mi][0].y, av[mi][1].y,
                         bv[ni].x, bv[ni].y);
        }

        const int j = i + 3;
        if (j < nk) {
            const uint32_t sb2 = sbase + (j & 3) * STAGE_BYTES;
            #pragma unroll
            for (int t = 0; t < 4; t++)
                asm volatile("cp.async.cg.shared.global [%0], [%1], 16;"
                             :: "r"(sb2 + sA + t * 4096),
                                "l"(gA + (size_t)(32 * t) * K + j * 32) : "memory");
            #pragma unroll
            for (int u = 0; u < 8; u++)
                asm volatile("cp.async.cg.shared.global [%0], [%1], 16;"
                             :: "r"(sb2 + 16384 + sA + u * 4096),
                                "l"(gB + (size_t)(32 * u) * K + j * 32) : "memory");
        }
        asm volatile("cp.async.commit_group;" ::: "memory");
    }

    // ---- epilogue ----
    const int p0 = perm8(2 * c);
    const int p1 = perm8(2 * c + 1);
    const int perm8g = perm8(g);
    const bool permStore = (emode == 1 || emode == 3);
    #pragma unroll
    for (int mi = 0; mi < 4; mi++) {
        const int r0 = by * 128 + wm * 64 + mi * 16 + g;
        #pragma unroll
        for (int ni = 0; ni < 8; ni++) {
            const int colg = bx * 256 + wn * 64 + ni * 8;
            const float bb0 = bias[colg + 2 * c];
            const float bb1 = bias[colg + 2 * c + 1];
            float v00 = acc[mi][ni][0] + bb0;
            float v01 = acc[mi][ni][1] + bb1;
            float v10 = acc[mi][ni][2] + bb0;
            float v11 = acc[mi][ni][3] + bb1;
            if (emode == 1) {
                v00 = gelu_f(v00); v01 = gelu_f(v01);
                v10 = gelu_f(v10); v11 = gelu_f(v11);
            }
            if (emode == 1 || emode == 3 || emode == 4) {
                v00 = rna_tf32(v00); v01 = rna_tf32(v01);
                v10 = rna_tf32(v10); v11 = rna_tf32(v11);
            }
            if (emode == 4) {
                // V^T store: [b][h][d][T], token (key) permuted within 8-groups
                const int col0 = colg + 2 * c;
                const int b0   = r0 >> 11;
                const int tb   = (r0 & 2047) & ~7;
                float* vb = vt + ((size_t)(b0 * 16 + (col0 >> 6)) * 64 + (col0 & 63)) * 2048
                               + tb + perm8g;
                vb[0]        = v00;
                vb[2048]     = v01;
                vb[8]        = v10;
                vb[2048 + 8] = v11;
            } else if (permStore) {
                float* c0 = C + (size_t)r0 * N + colg;
                float* c1 = C + (size_t)(r0 + 8) * N + colg;
                c0[p0] = v00; c0[p1] = v01;
                c1[p0] = v10; c1[p1] = v11;
            } else {
                if (emode == 2) {
                    const float* rr0 = res + (size_t)r0 * N + colg + 2 * c;
                    const float* rr1 = res + (size_t)(r0 + 8) * N + colg + 2 * c;
                    v00 += rr0[0]; v01 += rr0[1];
                    v10 += rr1[0]; v11 += rr1[1];
                }
                float2 o0; o0.x = v00; o0.y = v01;
                float2 o1; o1.x = v10; o1.y = v11;
                *(float2*)(C + (size_t)r0 * N + colg + 2 * c) = o0;
                *(float2*)(C + (size_t)(r0 + 8) * N + colg + 2 * c) = o1;
            }
        }
    }
}

// ---------------- tensor-core flash attention + residual ----------------------
// 128 q-rows per CTA, 8 warps (m16 each). K and V^T double-buffered.
// smem: K[2][64x64] | VT[2][64x64] | P[8][16x64]  = 96KB
#define AVT0 32768
#define AP   65536
#define ATT_SMEM 98304

__global__ __launch_bounds__(256, 2)
void attn_kernel(const float* __restrict__ x, float* __restrict__ x1,
                 float* __restrict__ x1r)
{
    extern __shared__ float sm[];
    const uint32_t sbase = smem_u32(sm);

    const int qt = gridDim.x - 1 - blockIdx.x;   // heavy tiles first
    const int bh = blockIdx.y;
    const int b = bh >> 4, h = bh & 15;
    const int tid = threadIdx.x, lane = tid & 31, w = tid >> 5;
    const int g = lane >> 2, c = lane & 3;

    const size_t headoff = (size_t)b * T * H + (size_t)h * HD;
    const float* Qg  = g_q + headoff;
    const float* Kg  = g_k + headoff;
    const float* VTg = g_vt + (size_t)bh * HD * T;

    const int lrow = tid >> 2;            // 0..63
    const int lc4x = (tid & 3) << 2;      // base float4 index {0,4,8,12}
    const float* kgp  = Kg  + (size_t)lrow * H + lc4x * 4;
    const float* vtgp = VTg + (size_t)lrow * T + lc4x * 4;
    uint32_t lso[4];
    #pragma unroll
    for (int i = 0; i < 4; i++) {
        int c4 = lc4x + i;
        lso[i] = (uint32_t)(lrow * 256 + ((((c4 >> 1) ^ (lrow & 7)) << 5)) + ((c4 & 1) << 4));
    }

    const int nkt = 2 * qt + 2;

    #pragma unroll
    for (int i = 0; i < 4; i++) {
        asm volatile("cp.async.cg.shared.global [%0], [%1], 16;"
                     :: "r"(sbase + lso[i]), "l"(kgp + i * 4) : "memory");
        asm volatile("cp.async.cg.shared.global [%0], [%1], 16;"
                     :: "r"(sbase + AVT0 + lso[i]), "l"(vtgp + i * 4) : "memory");
    }
    asm volatile("cp.async.commit_group;" ::: "memory");

    float qa[8][4];
    {
        const int r0 = qt * 128 + w * 16 + g;
        const float* q0 = Qg + (size_t)r0 * H;
        const float* q1 = q0 + 8 * H;
        #pragma unroll
        for (int k8 = 0; k8 < 8; k8++) {
            float2 v0 = *(const float2*)(q0 + k8 * 8 + 2 * c);
            float2 v1 = *(const float2*)(q1 + k8 * 8 + 2 * c);
            qa[k8][0] = v0.x * 0.03125f;
            qa[k8][2] = v0.y * 0.03125f;
            qa[k8][1] = v1.x * 0.03125f;
            qa[k8][3] = v1.y * 0.03125f;
        }
    }

    float o[8][4];
    #pragma unroll
    for (int nt = 0; nt < 8; nt++)
        #pragma unroll
        for (int r = 0; r < 4; r++) o[nt][r] = 0.0f;
    float mrow0 = -1e30f, mrow1 = -1e30f, lrow0 = 0.0f, lrow1 = 0.0f;

    const uint32_t pbase = sbase + AP + w * 4096;
    const int rowlo = qt * 128 + w * 16;
    const int row0 = rowlo + g;
    const int pc0 = (c < 2) ? 4 * c : 4 * (c - 2) + 1;

    for (int kt = 0; kt < nkt; kt++) {
        const uint32_t buf = (kt & 1) ? 16384u : 0u;
        asm volatile("cp.async.wait_group 0;" ::: "memory");
        __syncthreads();

        if (kt + 1 < nkt) {
            const uint32_t nb = (kt & 1) ? 0u : 16384u;
            const float* ks = kgp  + (size_t)(kt + 1) * 64 * H;
            const float* vs = vtgp + (kt + 1) * 64;
            #pragma unroll
            for (int i = 0; i < 4; i++) {
                asm volatile("cp.async.cg.shared.global [%0], [%1], 16;"
                             :: "r"(sbase + nb + lso[i]), "l"(ks + i * 4) : "memory");
                asm volatile("cp.async.cg.shared.global [%0], [%1], 16;"
                             :: "r"(sbase + AVT0 + nb + lso[i]), "l"(vs + i * 4) : "memory");
            }
        }
        asm volatile("cp.async.commit_group;" ::: "memory");

        const int ktbase = kt * 64;
        const bool active = (ktbase <= rowlo + 15);
        if (active) {
            const uint32_t kbuf  = sbase + buf;
            const uint32_t vtbuf = sbase + AVT0 + buf;

            float sacc[8][4];
            #pragma unroll
            for (int nt = 0; nt < 8; nt++)
                #pragma unroll
                for (int r = 0; r < 4; r++) sacc[nt][r] = 0.0f;
            #pragma unroll
            for (int k8 = 0; k8 < 8; k8++) {
                const uint32_t ab = kbuf + (uint32_t)(((k8 ^ g) << 5) + (c << 3));
                uint2 bf[8];
                #pragma unroll
                for (int nt = 0; nt < 8; nt++)
                    bf[nt] = lds64(ab + (uint32_t)((nt * 8 + g) * 256));
                #pragma unroll
                for (int nt = 0; nt < 8; nt++)
                    mma8(sacc[nt],
                         __float_as_uint(qa[k8][0]), __float_as_uint(qa[k8][1]),
                         __float_as_uint(qa[k8][2]), __float_as_uint(qa[k8][3]),
                         bf[nt].x, bf[nt].y);
            }

            if (ktbase + 63 > rowlo) {
                #pragma unroll
                for (int nt = 0; nt < 8; nt++) {
                    const int colb = ktbase + nt * 8 + 2 * c;
                    if (colb     > row0)     sacc[nt][0] = -1e30f;
                    if (colb + 1 > row0)     sacc[nt][1] = -1e30f;
                    if (colb     > row0 + 8) sacc[nt][2] = -1e30f;
                    if (colb + 1 > row0 + 8) sacc[nt][3] = -1e30f;
                }
            }

            float mx0 = -1e30f, mx1 = -1e30f;
            #pragma unroll
            for (int nt = 0; nt < 8; nt++) {
                mx0 = fmaxf(mx0, fmaxf(sacc[nt][0], sacc[nt][1]));
                mx1 = fmaxf(mx1, fmaxf(sacc[nt][2], sacc[nt][3]));
            }
            mx0 = fmaxf(mx0, __shfl_xor_sync(0xffffffffu, mx0, 1));
            mx0 = fmaxf(mx0, __shfl_xor_sync(0xffffffffu, mx0, 2));
            mx1 = fmaxf(mx1, __shfl_xor_sync(0xffffffffu, mx1, 1));
            mx1 = fmaxf(mx1, __shfl_xor_sync(0xffffffffu, mx1, 2));
            const float mn0 = fmaxf(mrow0, mx0);
            const float mn1 = fmaxf(mrow1, mx1);
            const float al0 = __expf(mrow0 - mn0);
            const float al1 = __expf(mrow1 - mn1);
            mrow0 = mn0; mrow1 = mn1;

            float rs0 = 0.0f, rs1 = 0.0f;
            #pragma unroll
            for (int nt = 0; nt < 8; nt++) {
                float p00 = __expf(sacc[nt][0] - mn0);
                float p01 = __expf(sacc[nt][1] - mn0);
                float p10 = __expf(sacc[nt][2] - mn1);
                float p11 = __expf(sacc[nt][3] - mn1);
                rs0 += p00 + p01;
                rs1 += p10 + p11;
                const uint32_t a0 = pbase + (uint32_t)(g * 256 + ((nt ^ g) << 5) + pc0 * 4);
                sm[(a0 - sbase) >> 2]              = rna_tf32(p00);
                sm[((a0 + 8) - sbase) >> 2]        = rna_tf32(p01);
                sm[((a0 + 2048) - sbase) >> 2]     = rna_tf32(p10);
                sm[((a0 + 2048 + 8) - sbase) >> 2] = rna_tf32(p11);
            }
            rs0 += __shfl_xor_sync(0xffffffffu, rs0, 1);
            rs0 += __shfl_xor_sync(0xffffffffu, rs0, 2);
            rs1 += __shfl_xor_sync(0xffffffffu, rs1, 1);
            rs1 += __shfl_xor_sync(0xffffffffu, rs1, 2);
            lrow0 = lrow0 * al0 + rs0;
            lrow1 = lrow1 * al1 + rs1;
            #pragma unroll
            for (int nt = 0; nt < 8; nt++) {
                o[nt][0] *= al0; o[nt][1] *= al0;
                o[nt][2] *= al1; o[nt][3] *= al1;
            }
            __syncwarp();

            #pragma unroll
            for (int k8 = 0; k8 < 8; k8++) {
                const uint32_t off = (uint32_t)(((k8 ^ g) << 5) + (c << 3));
                const uint2 pa0 = lds64(pbase + (uint32_t)(g * 256) + off);
                const uint2 pa1 = lds64(pbase + (uint32_t)(g * 256 + 2048) + off);
                #pragma unroll
                for (int nt = 0; nt < 8; nt++) {
                    const uint2 vb = lds64(vtbuf + (uint32_t)((nt * 8 + g) * 256) + off);
                    mma8(o[nt], pa0.x, pa1.x, pa0.y, pa1.y, vb.x, vb.y);
                }
            }
        }
    }

    const float inv0 = 1.0f / lrow0;
    const float inv1 = 1.0f / lrow1;
    const size_t rb0 = (size_t)b * T * H + (size_t)row0 * H + (size_t)h * HD;
    const size_t rb1 = rb0 + 8 * H;
    #pragma unroll
    for (int nt = 0; nt < 8; nt++) {
        const int d0 = nt * 8 + 2 * c;
        float v00 = o[nt][0] * inv0 + x[rb0 + d0];
        float v01 = o[nt][1] * inv0 + x[rb0 + d0 + 1];
        float v10 = o[nt][2] * inv1 + x[rb1 + d0];
        float v11 = o[nt][3] * inv1 + x[rb1 + d0 + 1];
        float2 t0; t0.x = v00; t0.y = v01;
        float2 t1; t1.x = v10; t1.y = v11;
        *(float2*)(x1 + rb0 + d0) = t0;
        *(float2*)(x1 + rb1 + d0) = t1;
        const size_t gb0 = rb0 + nt * 8;
        const size_t gb1 = rb1 + nt * 8;
        x1r[gb0 + pc0]     = rna_tf32(v00);
        x1r[gb0 + pc0 + 2] = rna_tf32(v01);
        x1r[gb1 + pc0]     = rna_tf32(v10);
        x1r[gb1 + pc0 + 2] = rna_tf32(v11);
    }
}

// ---------------- launch -----------------------------------------------------
extern "C" void kernel_launch(void* const* d_in, const int* in_sizes, int n_in,
                              void* d_out, int out_size)
{
    const float* x  = (const float*)d_in[0];
    const float* Wq = (const float*)d_in[1];
    const float* bq = (const float*)d_in[2];
    const float* Wk = (const float*)d_in[3];
    const float* bk = (const float*)d_in[4];
    const float* Wv = (const float*)d_in[5];
    const float* bv = (const float*)d_in[6];
    const float* W1 = (const float*)d_in[7];
    const float* b1 = (const float*)d_in[8];
    const float* W2 = (const float*)d_in[9];
    const float* b2 = (const float*)d_in[10];
    float* out = (float*)d_out;

    float *q, *k, *vt, *x1, *x1r, *xr, *h, *wqt, *wkt, *wvt, *w1t, *w2t;
    cudaGetSymbolAddress((void**)&q,    g_q);
    cudaGetSymbolAddress((void**)&k,    g_k);
    cudaGetSymbolAddress((void**)&vt,   g_vt);
    cudaGetSymbolAddress((void**)&x1,   g_x1);
    cudaGetSymbolAddress((void**)&x1r,  g_x1r);
    cudaGetSymbolAddress((void**)&xr,   g_xr);
    cudaGetSymbolAddress((void**)&h,    g_h);
    cudaGetSymbolAddress((void**)&wqt,  g_wqt);
    cudaGetSymbolAddress((void**)&wkt,  g_wkt);
    cudaGetSymbolAddress((void**)&wvt,  g_wvt);
    cudaGetSymbolAddress((void**)&w1t,  g_w1t);
    cudaGetSymbolAddress((void**)&w2t,  g_w2t);

    round_perm_k<<<(BT * H) / (256 * 8), 256>>>(x, xr, BT * H);
    transpose_all<<<11264, dim3(32, 8)>>>(Wq, Wk, Wv, W1, W2, wqt, wkt, wvt, w1t, w2t);

    cudaFuncSetAttribute(gemm_tf32, cudaFuncAttributeMaxDynamicSharedMemorySize, GEMM_SMEM);

    // QKV (q,k: rounded + d-permuted; v: rounded -> V^T layout)
    gemm_tf32<<<dim3(H / 256, BT / 128, 3), 256, GEMM_SMEM>>>(
        xr, wqt, wkt, wvt, bq, bk, bv, q, k, nullptr, nullptr, vt, H, H, 3);

    cudaFuncSetAttribute(attn_kernel, cudaFuncAttributeMaxDynamicSharedMemorySize, ATT_SMEM);
    attn_kernel<<<dim3(T / 128, BATCH * NHEAD), 256, ATT_SMEM>>>(x, x1, x1r);

    // MLP1
    gemm_tf32<<<dim3(FF / 256, BT / 128, 1), 256, GEMM_SMEM>>>(
        x1r, w1t, w1t, w1t, b1, b1, b1, h, h, h, nullptr, nullptr, H, FF, 1);

    // MLP2
    gemm_tf32<<<dim3(H / 256, BT / 128, 1), 256, GEMM_SMEM>>>(
        h, w2t, w2t, w2t, b2, b2, b2, out, out, out, x1, nullptr, FF, H, 2);
}

// round 9
// speedup vs baseline: 3.5001x; 1.6316x over previous
#include <cuda_runtime.h>
#include <cuda_fp16.h>
#include <math.h>
#include <stdint.h>

#define BATCH 4
#define T 2048
#define H 1024
#define NHEAD 16
#define HD 64
#define FF 4096
#define BT (BATCH * T)   // 8192 rows

// ---------------- scratch (allocation-free: __device__ globals) --------------
__device__ __half g_q[BT * H];     // fp16, d-perm16, pre-scaled 1/32
__device__ __half g_k[BT * H];     // fp16, d-perm16
__device__ __half g_vt[BT * H];    // V^T: [b][h][d][T], fp16, key-perm16
__device__ float  g_x1[BT * H];    // x + attn_out (exact fp32)
__device__ __half g_x1r[BT * H];   // fp16, k-perm16 x1
__device__ __half g_xr[BT * H];    // fp16, k-perm16 x
__device__ __half g_h[BT * FF];    // fp16, k-perm16 gelu(x1@W1+b1)
__device__ __half g_wqt[H * H];    // transposed + fp16 + k-perm16 weights [N,K]
__device__ __half g_wkt[H * H];
__device__ __half g_wvt[H * H];
__device__ __half g_w1t[H * FF];   // [FF, H]
__device__ __half g_w2t[FF * H];   // [H, FF]

// ---------------- helpers ----------------------------------------------------
__device__ __forceinline__ uint32_t smem_u32(const void* p) {
    uint32_t a;
    asm("{ .reg .u64 t; cvta.to.shared.u64 t, %1; cvt.u32.u64 %0, t; }"
        : "=r"(a) : "l"(p));
    return a;
}
__device__ __forceinline__ float ftanh(float x) {
    float y;
    asm("tanh.approx.f32 %0, %1;" : "=f"(y) : "f"(x));
    return y;
}
__device__ __forceinline__ float gelu_f(float x) {
    return 0.5f * x * (1.0f + ftanh(0.7978845608028654f * (x + 0.044715f * x * x * x)));
}
// quad-interleave: logical k index l (0..15) -> physical position
// layout [0,1,8,9, 2,3,10,11, 4,5,12,13, 6,7,14,15]
__device__ __forceinline__ int perm16(int l) {
    return 4 * ((l & 7) >> 1) + 2 * (l >> 3) + (l & 1);
}
__device__ __forceinline__ uint32_t h2(float a, float b) {
    __half2 v = __floats2half2_rn(a, b);
    return *reinterpret_cast<uint32_t*>(&v);
}
__device__ __forceinline__ uint2 lds64(uint32_t addr) {
    uint2 v;
    asm volatile("ld.shared.v2.b32 {%0, %1}, [%2];" : "=r"(v.x), "=r"(v.y) : "r"(addr));
    return v;
}
__device__ __forceinline__ void sts32(uint32_t addr, uint32_t v) {
    asm volatile("st.shared.b32 [%0], %1;" :: "r"(addr), "r"(v) : "memory");
}
__device__ __forceinline__ void mma16(float* d, uint32_t a0, uint32_t a1, uint32_t a2,
                                      uint32_t a3, uint32_t b0, uint32_t b1) {
    asm volatile(
        "mma.sync.aligned.m16n8k16.row.col.f32.f16.f16.f32 "
        "{%0,%1,%2,%3}, {%4,%5,%6,%7}, {%8,%9}, {%0,%1,%2,%3};"
        : "+f"(d[0]), "+f"(d[1]), "+f"(d[2]), "+f"(d[3])
        : "r"(a0), "r"(a1), "r"(a2), "r"(a3), "r"(b0), "r"(b1));
}

// ---------------- prep kernels ------------------------------------------------
// fp32 -> fp16 with perm16 on contiguous 16-groups
__global__ void round_perm_k(const float* __restrict__ in, __half* __restrict__ out, int n) {
    int i = (blockIdx.x * blockDim.x + threadIdx.x) * 16;
    if (i < n) {
        float f[16];
        #pragma unroll
        for (int j = 0; j < 4; j++)
            *(float4*)(f + 4 * j) = *(const float4*)(in + i + 4 * j);
        uint4 a, b;
        a.x = h2(f[0], f[1]);   a.y = h2(f[8], f[9]);
        a.z = h2(f[2], f[3]);   a.w = h2(f[10], f[11]);
        b.x = h2(f[4], f[5]);   b.y = h2(f[12], f[13]);
        b.z = h2(f[6], f[7]);   b.w = h2(f[14], f[15]);
        *(uint4*)(out + i)     = a;
        *(uint4*)(out + i + 8) = b;
    }
}

// all five weight transposes (fp32 [K,N] -> fp16 [N,K] with perm16 on k)
__global__ void transpose_all(const float* __restrict__ Wq, const float* __restrict__ Wk,
                              const float* __restrict__ Wv, const float* __restrict__ W1,
                              const float* __restrict__ W2,
                              __half* __restrict__ wqt, __half* __restrict__ wkt,
                              __half* __restrict__ wvt, __half* __restrict__ w1t,
                              __half* __restrict__ w2t)
{
    __shared__ float t[32][33];
    const int bid = blockIdx.x;
    const float* W; __half* Wt; int K, N, tile;
    if (bid < 1024)      { W = Wq; Wt = wqt; K = H;  N = H;  tile = bid; }
    else if (bid < 2048) { W = Wk; Wt = wkt; K = H;  N = H;  tile = bid - 1024; }
    else if (bid < 3072) { W = Wv; Wt = wvt; K = H;  N = H;  tile = bid - 2048; }
    else if (bid < 7168) { W = W1; Wt = w1t; K = H;  N = FF; tile = bid - 3072; }
    else                 { W = W2; Wt = w2t; K = FF; N = H;  tile = bid - 7168; }
    const int ntx = N >> 5;
    const int n0 = (tile % ntx) * 32, k0 = (tile / ntx) * 32;
    const int tx = threadIdx.x, ty = threadIdx.y;
    #pragma unroll
    for (int j = ty; j < 32; j += 8)
        t[j][tx] = W[(size_t)(k0 + j) * N + n0 + tx];
    __syncthreads();
    const int kk = k0 + tx;
    const int kphys = (kk & ~15) + perm16(kk & 15);
    #pragma unroll
    for (int j = ty; j < 32; j += 8)
        Wt[(size_t)(n0 + j) * K + kphys] = __float2half_rn(t[tx][j]);
}

// ---------------- fp16 mma.sync GEMM ------------------------------------------
// C[M, 256-tile] = A[M,Kperm] @ Bt[N,Kperm]^T, fp16 operands, fp32 accum.
// CTA 128x256, warp 64x64, BK=64 (128B rows), 4 stages, lookahead 3.
// Swizzle: 16B chunk ^ (row&7). One lds64 per fragment quad.
// modes: 1 gelu->fp16 perm, 2 float+res, 3 q/k fp16 perm (z0 scaled 1/32; z2 -> VT)
#define STAGE_BYTES 49152                 // 16KB A + 32KB B
#define GEMM_SMEM   (4 * STAGE_BYTES)     // 196608

__global__ __launch_bounds__(256, 1)
void gemm_fp16(const __half* __restrict__ A,
               const __half* __restrict__ B0t, const __half* __restrict__ B1t,
               const __half* __restrict__ B2t,
               const float* __restrict__ bias0, const float* __restrict__ bias1,
               const float* __restrict__ bias2,
               void* __restrict__ C0, void* __restrict__ C1, void* __restrict__ C2,
               const float* __restrict__ res, __half* __restrict__ vt,
               int K, int N, int mode)
{
    extern __shared__ char sf[];
    const uint32_t sbase = smem_u32(sf);

    const __half* Bt = B0t; const float* bias = bias0; void* Cp = C0;
    if (blockIdx.z == 1) { Bt = B1t; bias = bias1; Cp = C1; }
    else if (blockIdx.z == 2) { Bt = B2t; bias = bias2; Cp = C2; }
    int emode = mode;
    float oscale = 1.0f;
    if (mode == 3) {
        if (blockIdx.z == 2) emode = 4;
        else if (blockIdx.z == 0) oscale = 0.03125f;
    }

    const int tid  = threadIdx.x;
    const int lane = tid & 31;
    const int w    = tid >> 5;
    const int g    = lane >> 2;
    const int c    = lane & 3;
    const int wm   = w & 1;
    const int wn   = w >> 1;
    const int bx = blockIdx.x, by = blockIdx.y;
    const int nk = K >> 6;

    const int lrow = tid >> 3;
    const int cj   = tid & 7;
    const uint32_t sA = (uint32_t)(lrow * 128 + ((cj ^ (lrow & 7)) << 4));
    const __half* gA = A  + (size_t)(by * 128 + lrow) * K + cj * 8;
    const __half* gB = Bt + (size_t)(bx * 256 + lrow) * K + cj * 8;

    #pragma unroll
    for (int s = 0; s < 3; s++) {
        const uint32_t sb = sbase + s * STAGE_BYTES;
        #pragma unroll
        for (int t = 0; t < 4; t++)
            asm volatile("cp.async.cg.shared.global [%0], [%1], 16;"
                         :: "r"(sb + sA + t * 4096),
                            "l"(gA + (size_t)(32 * t) * K + s * 64) : "memory");
        #pragma unroll
        for (int u = 0; u < 8; u++)
            asm volatile("cp.async.cg.shared.global [%0], [%1], 16;"
                         :: "r"(sb + 16384 + sA + u * 4096),
                            "l"(gB + (size_t)(32 * u) * K + s * 64) : "memory");
        asm volatile("cp.async.commit_group;" ::: "memory");
    }

    float acc[4][8][4];
    #pragma unroll
    for (int mi = 0; mi < 4; mi++)
        #pragma unroll
        for (int ni = 0; ni < 8; ni++)
            #pragma unroll
            for (int r = 0; r < 4; r++) acc[mi][ni][r] = 0.0f;

    const uint32_t abase = (uint32_t)((wm * 64 + g) * 128);
    const uint32_t bbase = (uint32_t)(16384 + (wn * 64 + g) * 128);
    uint32_t coff[4];
    #pragma unroll
    for (int s = 0; s < 4; s++)
        coff[s] = (uint32_t)((((2 * s + (c >> 1)) ^ g) << 4) + (c & 1) * 8);

    for (int i = 0; i < nk; i++) {
        asm volatile("cp.async.wait_group 2;" ::: "memory");
        __syncthreads();

        const int j = i + 3;
        if (j < nk) {
            const uint32_t sb2 = sbase + (j & 3) * STAGE_BYTES;
            #pragma unroll
            for (int t = 0; t < 4; t++)
                asm volatile("cp.async.cg.shared.global [%0], [%1], 16;"
                             :: "r"(sb2 + sA + t * 4096),
                                "l"(gA + (size_t)(32 * t) * K + j * 64) : "memory");
            #pragma unroll
            for (int u = 0; u < 8; u++)
                asm volatile("cp.async.cg.shared.global [%0], [%1], 16;"
                             :: "r"(sb2 + 16384 + sA + u * 4096),
                                "l"(gB + (size_t)(32 * u) * K + j * 64) : "memory");
        }
        asm volatile("cp.async.commit_group;" ::: "memory");

        const uint32_t sb = sbase + (i & 3) * STAGE_BYTES;
        #pragma unroll
        for (int s = 0; s < 4; s++) {
            const uint32_t off = coff[s];
            uint2 av[4][2];
            #pragma unroll
            for (int mi = 0; mi < 4; mi++) {
                av[mi][0] = lds64(sb + abase + mi * 2048 + off);
                av[mi][1] = lds64(sb + abase + mi * 2048 + 1024 + off);
            }
            uint2 bv[8];
            #pragma unroll
            for (int ni = 0; ni < 8; ni++)
                bv[ni] = lds64(sb + bbase + ni * 1024 + off);
            #pragma unroll
            for (int mi = 0; mi < 4; mi++)
                #pragma unroll
                for (int ni = 0; ni < 8; ni++)
                    mma16(acc[mi][ni],
                          av[mi][0].x, av[mi][1].x, av[mi][0].y, av[mi][1].y,
                          bv[ni].x, bv[ni].y);
        }
    }

    // ---- epilogue ----
    #pragma unroll
    for (int mi = 0; mi < 4; mi++) {
        const int r0 = by * 128 + wm * 64 + mi * 16 + g;
        #pragma unroll
        for (int ni = 0; ni < 8; ni++) {
            const int colg = bx * 256 + wn * 64 + ni * 8;
            const float bb0 = bias[colg + 2 * c];
            const float bb1 = bias[colg + 2 * c + 1];
            float v00 = acc[mi][ni][0] + bb0;
            float v01 = acc[mi][ni][1] + bb1;
            float v10 = acc[mi][ni][2] + bb0;
            float v11 = acc[mi][ni][3] + bb1;
            if (emode == 1) {
                v00 = gelu_f(v00); v01 = gelu_f(v01);
                v10 = gelu_f(v10); v11 = gelu_f(v11);
            }
            if (emode == 2) {
                float* C = (float*)Cp;
                const float* rr0 = res + (size_t)r0 * N + colg + 2 * c;
                const float* rr1 = res + (size_t)(r0 + 8) * N + colg + 2 * c;
                float2 o0; o0.x = v00 + rr0[0]; o0.y = v01 + rr0[1];
                float2 o1; o1.x = v10 + rr1[0]; o1.y = v11 + rr1[1];
                *(float2*)(C + (size_t)r0 * N + colg + 2 * c) = o0;
                *(float2*)(C + (size_t)(r0 + 8) * N + colg + 2 * c) = o1;
            } else if (emode == 4) {
                // V^T: [b][h][d][T], token perm16'd within 16-groups
                const int col0 = colg + 2 * c;          // channel (even)
                const int b0   = r0 >> 11;
                const int head = col0 >> 6;
                const int d    = col0 & 63;
                const int t16  = (r0 & 2047) & ~15;
                const int tpp  = 4 * (g >> 1) + (g & 1);   // perm16(g), g<8
                __half* vb = vt + ((size_t)(b0 * 16 + head) * 64 + d) * 2048 + t16 + tpp;
                vb[0]        = __float2half_rn(v00);    // (d,   token r0)
                vb[2048]     = __float2half_rn(v01);    // (d+1, token r0)
                vb[2]        = __float2half_rn(v10);    // (d,   token r0+8): perm16(g+8)=tpp+2
                vb[2048 + 2] = __float2half_rn(v11);
            } else {
                // fp16 + perm16 column store (emode 1 or 3)
                v00 *= oscale; v01 *= oscale; v10 *= oscale; v11 *= oscale;
                __half* C = (__half*)Cp;
                const int base16 = colg & ~15;
                const int poff = 4 * c + 2 * (ni & 1);
                *(uint32_t*)(C + (size_t)r0 * N + base16 + poff)       = h2(v00, v01);
                *(uint32_t*)(C + (size_t)(r0 + 8) * N + base16 + poff) = h2(v10, v11);
            }
        }
    }
}

// ---------------- fp16 tensor-core flash attention + residual ------------------
// 128 q-rows per CTA, 8 warps (m16 each). K and V^T double-buffered (8KB tiles).
// smem: K0@0 K1@8192 | VT0@16384 VT1@24576 | P@32768 (w*2048) -> 48KB
#define AK0  0
#define AVT0 16384
#define AP   32768
#define ATT_SMEM 49152

__global__ __launch_bounds__(256, 2)
void attn_kernel(const float* __restrict__ x, float* __restrict__ x1,
                 __half* __restrict__ x1r)
{
    extern __shared__ char sm[];
    const uint32_t sbase = smem_u32(sm);

    const int qt = gridDim.x - 1 - blockIdx.x;   // heavy tiles first
    const int bh = blockIdx.y;
    const int b = bh >> 4, h = bh & 15;
    const int tid = threadIdx.x, lane = tid & 31, w = tid >> 5;
    const int g = lane >> 2, c = lane & 3;

    const size_t headoff = (size_t)b * T * H + (size_t)h * HD;
    const __half* Qg  = g_q + headoff;
    const __half* Kg  = g_k + headoff;
    const __half* VTg = g_vt + (size_t)bh * HD * T;

    const int lrow = tid >> 2;            // 0..63
    const int lch0 = (tid & 3) * 2;
    uint32_t lso[2];
    #pragma unroll
    for (int i = 0; i < 2; i++)
        lso[i] = (uint32_t)(lrow * 128 + (((lch0 + i) ^ (lrow & 7)) << 4));
    const __half* kgp  = Kg  + (size_t)lrow * H + lch0 * 8;
    const __half* vtgp = VTg + (size_t)lrow * T + lch0 * 8;

    const int nkt = 2 * qt + 2;

    #pragma unroll
    for (int i = 0; i < 2; i++) {
        asm volatile("cp.async.cg.shared.global [%0], [%1], 16;"
                     :: "r"(sbase + AK0 + lso[i]), "l"(kgp + i * 8) : "memory");
        asm volatile("cp.async.cg.shared.global [%0], [%1], 16;"
                     :: "r"(sbase + AVT0 + lso[i]), "l"(vtgp + i * 8) : "memory");
    }
    asm volatile("cp.async.commit_group;" ::: "memory");

    uint32_t qa[4][4];
    {
        const int r0 = qt * 128 + w * 16 + g;
        const __half* q0 = Qg + (size_t)r0 * H;
        #pragma unroll
        for (int s = 0; s < 4; s++) {
            uint2 t0 = *(const uint2*)(q0 + s * 16 + c * 4);
            uint2 t1 = *(const uint2*)(q0 + 8 * H + s * 16 + c * 4);
            qa[s][0] = t0.x; qa[s][1] = t1.x; qa[s][2] = t0.y; qa[s][3] = t1.y;
        }
    }

    float o[8][4];
    #pragma unroll
    for (int nt = 0; nt < 8; nt++)
        #pragma unroll
        for (int r = 0; r < 4; r++) o[nt][r] = 0.0f;
    float mrow0 = -1e30f, mrow1 = -1e30f, lsum0 = 0.0f, lsum1 = 0.0f;

    const uint32_t pbase = sbase + AP + w * 2048;
    const int rowlo = qt * 128 + w * 16;
    const int row0 = rowlo + g;
    uint32_t coff[4];
    #pragma unroll
    for (int s = 0; s < 4; s++)
        coff[s] = (uint32_t)((((2 * s + (c >> 1)) ^ g) << 4) + (c & 1) * 8);

    for (int kt = 0; kt < nkt; kt++) {
        const uint32_t buf = (kt & 1) ? 8192u : 0u;
        asm volatile("cp.async.wait_group 0;" ::: "memory");
        __syncthreads();

        if (kt + 1 < nkt) {
            const uint32_t nb = (kt & 1) ? 0u : 8192u;
            const __half* ks = kgp  + (size_t)(kt + 1) * 64 * H;
            const __half* vs = vtgp + (kt + 1) * 64;
            #pragma unroll
            for (int i = 0; i < 2; i++) {
                asm volatile("cp.async.cg.shared.global [%0], [%1], 16;"
                             :: "r"(sbase + AK0 + nb + lso[i]), "l"(ks + i * 8) : "memory");
                asm volatile("cp.async.cg.shared.global [%0], [%1], 16;"
                             :: "r"(sbase + AVT0 + nb + lso[i]), "l"(vs + i * 8) : "memory");
            }
        }
        asm volatile("cp.async.commit_group;" ::: "memory");

        const int ktbase = kt * 64;
        const bool active = (ktbase <= rowlo + 15);
        if (active) {
            const uint32_t kbuf  = sbase + AK0 + buf;
            const uint32_t vtbuf = sbase + AVT0 + buf;

            // S = Q @ K^T
            float sacc[8][4];
            #pragma unroll
            for (int nt = 0; nt < 8; nt++)
                #pragma unroll
                for (int r = 0; r < 4; r++) sacc[nt][r] = 0.0f;
            #pragma unroll
            for (int s = 0; s < 4; s++) {
                uint2 bf[8];
                #pragma unroll
                for (int nt = 0; nt < 8; nt++)
                    bf[nt] = lds64(kbuf + (uint32_t)((nt * 8 + g) * 128) + coff[s]);
                #pragma unroll
                for (int nt = 0; nt < 8; nt++)
                    mma16(sacc[nt], qa[s][0], qa[s][1], qa[s][2], qa[s][3],
                          bf[nt].x, bf[nt].y);
            }

            if (ktbase + 63 > rowlo) {
                #pragma unroll
                for (int nt = 0; nt < 8; nt++) {
                    const int colb = ktbase + nt * 8 + 2 * c;
                    if (colb     > row0)     sacc[nt][0] = -1e30f;
                    if (colb + 1 > row0)     sacc[nt][1] = -1e30f;
                    if (colb     > row0 + 8) sacc[nt][2] = -1e30f;
                    if (colb + 1 > row0 + 8) sacc[nt][3] = -1e30f;
                }
            }

            float mx0 = -1e30f, mx1 = -1e30f;
            #pragma unroll
            for (int nt = 0; nt < 8; nt++) {
                mx0 = fmaxf(mx0, fmaxf(sacc[nt][0], sacc[nt][1]));
                mx1 = fmaxf(mx1, fmaxf(sacc[nt][2], sacc[nt][3]));
            }
            mx0 = fmaxf(mx0, __shfl_xor_sync(0xffffffffu, mx0, 1));
            mx0 = fmaxf(mx0, __shfl_xor_sync(0xffffffffu, mx0, 2));
            mx1 = fmaxf(mx1, __shfl_xor_sync(0xffffffffu, mx1, 1));
            mx1 = fmaxf(mx1, __shfl_xor_sync(0xffffffffu, mx1, 2));
            const float mn0 = fmaxf(mrow0, mx0);
            const float mn1 = fmaxf(mrow1, mx1);
            const float al0 = __expf(mrow0 - mn0);
            const float al1 = __expf(mrow1 - mn1);
            mrow0 = mn0; mrow1 = mn1;

            float rs0 = 0.0f, rs1 = 0.0f;
            #pragma unroll
            for (int nt = 0; nt < 8; nt++) {
                float p00 = __expf(sacc[nt][0] - mn0);
                float p01 = __expf(sacc[nt][1] - mn0);
                float p10 = __expf(sacc[nt][2] - mn1);
                float p11 = __expf(sacc[nt][3] - mn1);
                rs0 += p00 + p01;
                rs1 += p10 + p11;
                // P store: fp16, key perm16, chunk^row swizzle
                const uint32_t ch = (uint32_t)((((nt >> 1) * 2 + (c >> 1)) ^ g));
                const uint32_t a0 = pbase + (uint32_t)(g * 128) + (ch << 4)
                                  + (uint32_t)(8 * (c & 1) + 4 * (nt & 1));
                sts32(a0, h2(p00, p01));
                sts32(a0 + 1024, h2(p10, p11));
            }
            rs0 += __shfl_xor_sync(0xffffffffu, rs0, 1);
            rs0 += __shfl_xor_sync(0xffffffffu, rs0, 2);
            rs1 += __shfl_xor_sync(0xffffffffu, rs1, 1);
            rs1 += __shfl_xor_sync(0xffffffffu, rs1, 2);
            lsum0 = lsum0 * al0 + rs0;
            lsum1 = lsum1 * al1 + rs1;
            #pragma unroll
            for (int nt = 0; nt < 8; nt++) {
                o[nt][0] *= al0; o[nt][1] *= al0;
                o[nt][2] *= al1; o[nt][3] *= al1;
            }
            __syncwarp();

            // O += P @ V
            #pragma unroll
            for (int s = 0; s < 4; s++) {
                const uint2 pa0 = lds64(pbase + (uint32_t)(g * 128) + coff[s]);
                const uint2 pa1 = lds64(pbase + (uint32_t)(g * 128 + 1024) + coff[s]);
                #pragma unroll
                for (int nt = 0; nt < 8; nt++) {
                    const uint2 vb = lds64(vtbuf + (uint32_t)((nt * 8 + g) * 128) + coff[s]);
                    mma16(o[nt], pa0.x, pa1.x, pa0.y, pa1.y, vb.x, vb.y);
                }
            }
        }
    }

    // epilogue: x1 = x + O/l (fp32 exact), x1r = fp16 perm16
    const float inv0 = 1.0f / lsum0;
    const float inv1 = 1.0f / lsum1;
    const size_t rb0 = (size_t)b * T * H + (size_t)row0 * H + (size_t)h * HD;
    const size_t rb1 = rb0 + 8 * H;
    #pragma unroll
    for (int nt = 0; nt < 8; nt++) {
        const int d0 = nt * 8 + 2 * c;
        const float v00 = o[nt][0] * inv0 + x[rb0 + d0];
        const float v01 = o[nt][1] * inv0 + x[rb0 + d0 + 1];
        const float v10 = o[nt][2] * inv1 + x[rb1 + d0];
        const float v11 = o[nt][3] * inv1 + x[rb1 + d0 + 1];
        float2 t0; t0.x = v00; t0.y = v01;
        float2 t1; t1.x = v10; t1.y = v11;
        *(float2*)(x1 + rb0 + d0) = t0;
        *(float2*)(x1 + rb1 + d0) = t1;
        const int poff = (nt >> 1) * 16 + 4 * c + 2 * (nt & 1);
        *(uint32_t*)(x1r + rb0 + poff) = h2(v00, v01);
        *(uint32_t*)(x1r + rb1 + poff) = h2(v10, v11);
    }
}

// ---------------- launch -----------------------------------------------------
extern "C" void kernel_launch(void* const* d_in, const int* in_sizes, int n_in,
                              void* d_out, int out_size)
{
    const float* x  = (const float*)d_in[0];
    const float* Wq = (const float*)d_in[1];
    const float* bq = (const float*)d_in[2];
    const float* Wk = (const float*)d_in[3];
    const float* bk = (const float*)d_in[4];
    const float* Wv = (const float*)d_in[5];
    const float* bv = (const float*)d_in[6];
    const float* W1 = (const float*)d_in[7];
    const float* b1 = (const float*)d_in[8];
    const float* W2 = (const float*)d_in[9];
    const float* b2 = (const float*)d_in[10];
    float* out = (float*)d_out;

    __half *q, *k, *vt, *x1r, *xr, *h, *wqt, *wkt, *wvt, *w1t, *w2t;
    float *x1;
    cudaGetSymbolAddress((void**)&q,    g_q);
    cudaGetSymbolAddress((void**)&k,    g_k);
    cudaGetSymbolAddress((void**)&vt,   g_vt);
    cudaGetSymbolAddress((void**)&x1,   g_x1);
    cudaGetSymbolAddress((void**)&x1r,  g_x1r);
    cudaGetSymbolAddress((void**)&xr,   g_xr);
    cudaGetSymbolAddress((void**)&h,    g_h);
    cudaGetSymbolAddress((void**)&wqt,  g_wqt);
    cudaGetSymbolAddress((void**)&wkt,  g_wkt);
    cudaGetSymbolAddress((void**)&wvt,  g_wvt);
    cudaGetSymbolAddress((void**)&w1t,  g_w1t);
    cudaGetSymbolAddress((void**)&w2t,  g_w2t);

    round_perm_k<<<(BT * H) / (256 * 16), 256>>>(x, xr, BT * H);
    transpose_all<<<11264, dim3(32, 8)>>>(Wq, Wk, Wv, W1, W2, wqt, wkt, wvt, w1t, w2t);

    cudaFuncSetAttribute(gemm_fp16, cudaFuncAttributeMaxDynamicSharedMemorySize, GEMM_SMEM);

    // QKV (q: fp16 perm + 1/32 scale; k: fp16 perm; v -> V^T fp16)
    gemm_fp16<<<dim3(H / 256, BT / 128, 3), 256, GEMM_SMEM>>>(
        xr, wqt, wkt, wvt, bq, bk, bv, q, k, nullptr, nullptr, vt, H, H, 3);

    cudaFuncSetAttribute(attn_kernel, cudaFuncAttributeMaxDynamicSharedMemorySize, ATT_SMEM);
    attn_kernel<<<dim3(T / 128, BATCH * NHEAD), 256, ATT_SMEM>>>(x, x1, x1r);

    // MLP1: h = fp16(gelu(x1r @ W1t^T + b1)), perm16 cols
    gemm_fp16<<<dim3(FF / 256, BT / 128, 1), 256, GEMM_SMEM>>>(
        x1r, w1t, w1t, w1t, b1, b1, b1, h, h, h, nullptr, nullptr, H, FF, 1);

    // MLP2: out = h @ W2t^T + b2 + x1  (fp32 out)
    gemm_fp16<<<dim3(H / 256, BT / 128, 1), 256, GEMM_SMEM>>>(
        h, w2t, w2t, w2t, b2, b2, b2, out, out, out, x1, nullptr, FF, H, 2);
}